// round 2
// baseline (speedup 1.0000x reference)
#include <cuda_runtime.h>
#include <cuda_bf16.h>
#include <math.h>

#define N_AST 100000
#define E_AST 1250000
#define N_CFG 100000
#define E_CFG 1250000
#define NG 1024
#define HID 64
#define SEM 768

#define NMAX 100000

// ---------------- device scratch (static, allocation-free) ----------------
__device__ float  g_deg [2][NMAX];
__device__ float  g_dinv[2][NMAX];
__device__ float4 g_h   [2][NMAX * 16];   // [node][16 x float4] = 64 floats
__device__ float4 g_agg [2][NMAX * 16];
__device__ float4 g_pool[2][NG * 16];
__device__ float  g_tab [2][200 * 64];    // emb @ W1 lookup table

__device__ __forceinline__ void red_add_v4(float* addr, float4 v) {
    asm volatile("red.global.add.v4.f32 [%0], {%1, %2, %3, %4};"
                 :: "l"(addr), "f"(v.x), "f"(v.y), "f"(v.z), "f"(v.w)
                 : "memory");
}

// ---------------- kernels ----------------

// zero deg + pool buffers (replayed every call, keeps launch deterministic)
__global__ void k_zero() {
    int i = blockIdx.x * blockDim.x + threadIdx.x;
    if (i < NMAX) { g_deg[0][i] = 0.f; g_deg[1][i] = 0.f; }
    if (i < NG * 16) {
        g_pool[0][i] = make_float4(0.f, 0.f, 0.f, 0.f);
        g_pool[1][i] = make_float4(0.f, 0.f, 0.f, 0.f);
    }
}

// tab[s] = emb @ W1  (200 rows ast, 100 rows cfg)
__global__ void k_table(const float* __restrict__ embA, const float* __restrict__ W1A,
                        const float* __restrict__ embC, const float* __restrict__ W1C) {
    __shared__ float sx[64];
    int r = blockIdx.x, j = threadIdx.x;
    const float* emb; const float* W; float* tab; int row;
    if (r < 200) { emb = embA; W = W1A; tab = g_tab[0]; row = r; }
    else         { emb = embC; W = W1C; tab = g_tab[1]; row = r - 200; }
    sx[j] = emb[row * 64 + j];
    __syncthreads();
    float acc = 0.f;
#pragma unroll
    for (int k = 0; k < 64; k++) acc = fmaf(sx[k], W[k * 64 + j], acc);
    tab[row * 64 + j] = acc;
}

// degree count over dst
__global__ void k_deg(int s, const int* __restrict__ dst, int E) {
    int e = blockIdx.x * blockDim.x + threadIdx.x;
    if (e < E) atomicAdd(&g_deg[s][dst[e]], 1.0f);
}

// layer-1 node init: h = tab[type], agg = h * dinv^2, store dinv
__global__ void k_node1(int s, const int* __restrict__ type, int n) {
    int t = blockIdx.x * blockDim.x + threadIdx.x;
    int node = t >> 4, lane = t & 15;
    if (node >= n) return;
    float d = rsqrtf(g_deg[s][node] + 1.0f);
    if (lane == 0) g_dinv[s][node] = d;
    int ty = __ldg(&type[node]);
    float4 v = ((const float4*)g_tab[s])[ty * 16 + lane];
    g_h[s][node * 16 + lane] = v;
    float ss = d * d;
    g_agg[s][node * 16 + lane] = make_float4(v.x * ss, v.y * ss, v.z * ss, v.w * ss);
}

// edge message pass: agg[dst] += h[src] * dinv[src]*dinv[dst]
__global__ void k_edge(int s, const int* __restrict__ src, const int* __restrict__ dst, int E) {
    int t = blockIdx.x * blockDim.x + threadIdx.x;
    int e = t >> 4, lane = t & 15;
    if (e >= E) return;
    int u = __ldg(&src[e]);
    int v = __ldg(&dst[e]);
    float c = g_dinv[s][u] * g_dinv[s][v];
    float4 hv = g_h[s][u * 16 + lane];
    float4 m = make_float4(hv.x * c, hv.y * c, hv.z * c, hv.w * c);
    red_add_v4((float*)&g_agg[s][v * 16 + lane], m);
}

// layer-2: x = relu(agg + b1); h2 = x @ W2; agg <- h2 * dinv^2 ; h <- h2
__global__ void k_node2(int s, const float* __restrict__ W,
                        const float* __restrict__ b1, int n) {
    int j = threadIdx.x & 63;
    int sub = threadIdx.x >> 6;   // 0..3
    __shared__ float sx[4][64];
    float wcol[64];
#pragma unroll
    for (int k = 0; k < 64; k++) wcol[k] = W[k * 64 + j];
    float bj = b1[j];
    float* hh  = (float*)g_h[s];
    float* agg = (float*)g_agg[s];
    for (int base = blockIdx.x * 4; base < n; base += gridDim.x * 4) {
        int node = base + sub;
        float xv = 0.f;
        if (node < n) {
            xv = agg[node * 64 + j] + bj;
            xv = fmaxf(xv, 0.f);
        }
        sx[sub][j] = xv;
        __syncthreads();
        if (node < n) {
            float acc = 0.f;
#pragma unroll
            for (int k = 0; k < 64; k++) acc = fmaf(sx[sub][k], wcol[k], acc);
            float d = g_dinv[s][node];
            float ss = d * d;
            hh[node * 64 + j]  = acc;
            agg[node * 64 + j] = acc * ss;
        }
        __syncthreads();
    }
}

// pool: pool[batch[i]] += agg2[i] + b2
__global__ void k_pool(int s, const int* __restrict__ batch,
                       const float* __restrict__ b2, int n) {
    int t = blockIdx.x * blockDim.x + threadIdx.x;
    int node = t >> 4, lane = t & 15;
    if (node >= n) return;
    float4 bv = ((const float4*)b2)[lane];
    float4 v = g_agg[s][node * 16 + lane];
    v.x += bv.x; v.y += bv.y; v.z += bv.z; v.w += bv.w;
    int g = __ldg(&batch[node]);
    red_add_v4((float*)&g_pool[s][g * 16 + lane], v);
}

// fused epilogue: gate1, sem proj, gate2, layernorm, classifier. 1 block / graph, 64 thr.
__global__ void k_epilogue(const float* __restrict__ sem,
                           const float* __restrict__ Wg1, const float* __restrict__ bg1,
                           const float* __restrict__ Wsem, const float* __restrict__ bsem,
                           const float* __restrict__ Wg2, const float* __restrict__ bg2,
                           const float* __restrict__ ln_g, const float* __restrict__ ln_b,
                           const float* __restrict__ Wc, const float* __restrict__ bc,
                           float* __restrict__ out) {
    int g = blockIdx.x, j = threadIdx.x;  // 64 threads
    __shared__ float sa[64], sb[64], hs[64], hm[64];
    __shared__ float ssem[SEM];
    __shared__ float2 rbuf[64];

    float a = ((const float*)g_pool[0])[g * 64 + j];
    float b = ((const float*)g_pool[1])[g * 64 + j];
    sa[j] = a; sb[j] = b;
    for (int t = j; t < SEM; t += 64) ssem[t] = sem[g * SEM + t];
    __syncthreads();

    // gate 1
    float acc = bg1[j];
#pragma unroll
    for (int k = 0; k < 64; k++) acc = fmaf(sa[k], Wg1[k * 64 + j], acc);
#pragma unroll
    for (int k = 0; k < 64; k++) acc = fmaf(sb[k], Wg1[(64 + k) * 64 + j], acc);
    float g1 = 1.f / (1.f + expf(-acc));
    float hstruct = g1 * a + (1.f - g1) * b;

    // sem projection
    float acc2 = bsem[j];
#pragma unroll 8
    for (int k = 0; k < SEM; k++) acc2 = fmaf(ssem[k], Wsem[k * 64 + j], acc2);
    float hsem = fmaxf(acc2, 0.f);

    hs[j] = hstruct; hm[j] = hsem;
    __syncthreads();

    // gate 2
    float acc3 = bg2[j];
#pragma unroll
    for (int k = 0; k < 64; k++) acc3 = fmaf(hs[k], Wg2[k * 64 + j], acc3);
#pragma unroll
    for (int k = 0; k < 64; k++) acc3 = fmaf(hm[k], Wg2[(64 + k) * 64 + j], acc3);
    float g2 = 1.f / (1.f + expf(-acc3));
    float h = g2 * hstruct + (1.f - g2) * hsem;

    // layernorm stats
    rbuf[j] = make_float2(h, h * h);
    __syncthreads();
    for (int off = 32; off > 0; off >>= 1) {
        if (j < off) { rbuf[j].x += rbuf[j + off].x; rbuf[j].y += rbuf[j + off].y; }
        __syncthreads();
    }
    float mu  = rbuf[0].x * (1.f / 64.f);
    float var = rbuf[0].y * (1.f / 64.f) - mu * mu;
    float hn = (h - mu) * rsqrtf(var + 1e-5f) * ln_g[j] + ln_b[j];
    __syncthreads();

    // classifier (2 outputs)
    rbuf[j] = make_float2(hn * Wc[j * 2 + 0], hn * Wc[j * 2 + 1]);
    __syncthreads();
    for (int off = 32; off > 0; off >>= 1) {
        if (j < off) { rbuf[j].x += rbuf[j + off].x; rbuf[j].y += rbuf[j + off].y; }
        __syncthreads();
    }
    if (j == 0) {
        out[g * 2 + 0] = rbuf[0].x + bc[0];
        out[g * 2 + 1] = rbuf[0].y + bc[1];
    }
}

// ---------------- launch ----------------
extern "C" void kernel_launch(void* const* d_in, const int* in_sizes, int n_in,
                              void* d_out, int out_size) {
    const int*   ast_type  = (const int*)  d_in[0];
    const int*   ast_edge  = (const int*)  d_in[1];   // [2, E]: src=+0, dst=+E
    const int*   ast_batch = (const int*)  d_in[2];
    const int*   cfg_type  = (const int*)  d_in[3];
    const int*   cfg_edge  = (const int*)  d_in[4];
    const int*   cfg_batch = (const int*)  d_in[5];
    const float* sem       = (const float*)d_in[6];
    const float* ast_emb   = (const float*)d_in[7];
    const float* cfg_emb   = (const float*)d_in[8];
    const float* ast_W1    = (const float*)d_in[9];
    const float* ast_b1    = (const float*)d_in[10];
    const float* ast_W2    = (const float*)d_in[11];
    const float* ast_b2    = (const float*)d_in[12];
    const float* cfg_W1    = (const float*)d_in[13];
    const float* cfg_b1    = (const float*)d_in[14];
    const float* cfg_W2    = (const float*)d_in[15];
    const float* cfg_b2    = (const float*)d_in[16];
    const float* Wg1       = (const float*)d_in[17];
    const float* bg1       = (const float*)d_in[18];
    const float* Wsem      = (const float*)d_in[19];
    const float* bsem      = (const float*)d_in[20];
    const float* Wg2       = (const float*)d_in[21];
    const float* bg2       = (const float*)d_in[22];
    const float* ln_g      = (const float*)d_in[23];
    const float* ln_b      = (const float*)d_in[24];
    const float* Wc        = (const float*)d_in[25];
    const float* bc        = (const float*)d_in[26];
    float* out = (float*)d_out;

    k_zero<<<(NMAX + 255) / 256, 256>>>();
    k_table<<<300, 64>>>(ast_emb, ast_W1, cfg_emb, cfg_W1);

    k_deg<<<(E_AST + 255) / 256, 256>>>(0, ast_edge + E_AST, E_AST);
    k_deg<<<(E_CFG + 255) / 256, 256>>>(1, cfg_edge + E_CFG, E_CFG);

    k_node1<<<(N_AST * 16 + 255) / 256, 256>>>(0, ast_type, N_AST);
    k_node1<<<(N_CFG * 16 + 255) / 256, 256>>>(1, cfg_type, N_CFG);

    k_edge<<<(E_AST * 16 + 255) / 256, 256>>>(0, ast_edge, ast_edge + E_AST, E_AST);
    k_edge<<<(E_CFG * 16 + 255) / 256, 256>>>(1, cfg_edge, cfg_edge + E_CFG, E_CFG);

    k_node2<<<2048, 256>>>(0, ast_W2, ast_b1, N_AST);
    k_node2<<<2048, 256>>>(1, cfg_W2, cfg_b1, N_CFG);

    k_edge<<<(E_AST * 16 + 255) / 256, 256>>>(0, ast_edge, ast_edge + E_AST, E_AST);
    k_edge<<<(E_CFG * 16 + 255) / 256, 256>>>(1, cfg_edge, cfg_edge + E_CFG, E_CFG);

    k_pool<<<(N_AST * 16 + 255) / 256, 256>>>(0, ast_batch, ast_b2, N_AST);
    k_pool<<<(N_CFG * 16 + 255) / 256, 256>>>(1, cfg_batch, cfg_b2, N_CFG);

    k_epilogue<<<NG, 64>>>(sem, Wg1, bg1, Wsem, bsem, Wg2, bg2,
                           ln_g, ln_b, Wc, bc, out);
}

// round 4
// speedup vs baseline: 1.5305x; 1.5305x over previous
#include <cuda_runtime.h>
#include <cuda_bf16.h>
#include <math.h>

#define N_AST 100000
#define E_AST 1250000
#define NG 1024
#define HID 64
#define SEM 768
#define NMAX 100000
#define EMAX 1250000
#define SCAN_B 512
#define SCAN_NB 196   // ceil(100000/512)

// ---------------- device scratch (static, allocation-free) ----------------
__device__ int    g_deg   [2][NMAX];
__device__ int    g_rowptr[2][NMAX];
__device__ int    g_cursor[2][NMAX];
__device__ int    g_bsum  [2][SCAN_NB];
__device__ int    g_boff  [2][SCAN_NB];
__device__ int    g_csr   [2][EMAX];
__device__ float  g_dinv  [2][NMAX];
__device__ float4 g_h     [2][NMAX * 16];   // hh = h * dinv (64 floats/node)
__device__ float4 g_agg   [2][NMAX * 16];   // x buffer between layers
__device__ float4 g_pool  [2][NG * 16];
__device__ float  g_tab   [2][200 * 64];    // emb @ W1 lookup table

__device__ __forceinline__ void red_add_v4(float* addr, float4 v) {
    asm volatile("red.global.add.v4.f32 [%0], {%1, %2, %3, %4};"
                 :: "l"(addr), "f"(v.x), "f"(v.y), "f"(v.z), "f"(v.w)
                 : "memory");
}

// ---------------- kernels ----------------

__global__ void k_zero() {
    int i = blockIdx.x * blockDim.x + threadIdx.x;
    if (i < NMAX) { g_deg[0][i] = 0; g_deg[1][i] = 0; }
    if (i < NG * 16) {
        g_pool[0][i] = make_float4(0.f, 0.f, 0.f, 0.f);
        g_pool[1][i] = make_float4(0.f, 0.f, 0.f, 0.f);
    }
}

// tab[s] = emb @ W1  (200 rows ast, 100 rows cfg)
__global__ void k_table(const float* __restrict__ embA, const float* __restrict__ W1A,
                        const float* __restrict__ embC, const float* __restrict__ W1C) {
    __shared__ float sx[64];
    int r = blockIdx.x, j = threadIdx.x;
    const float* emb; const float* W; float* tab; int row;
    if (r < 200) { emb = embA; W = W1A; tab = g_tab[0]; row = r; }
    else         { emb = embC; W = W1C; tab = g_tab[1]; row = r - 200; }
    sx[j] = emb[row * 64 + j];
    __syncthreads();
    float acc = 0.f;
#pragma unroll
    for (int k = 0; k < 64; k++) acc = fmaf(sx[k], W[k * 64 + j], acc);
    tab[row * 64 + j] = acc;
}

// in-degree counts over dst, both graphs in one launch
__global__ void k_deg(const int* __restrict__ eA, const int* __restrict__ eC) {
    int t = blockIdx.x * blockDim.x + threadIdx.x;
    if (t >= 2 * EMAX) return;
    int s = t >= EMAX; int e = t - s * EMAX;
    const int* edge = s ? eC : eA;
    atomicAdd(&g_deg[s][__ldg(edge + EMAX + e)], 1);
}

// scan pass 1: per-block exclusive scan of deg -> rowptr (local), block totals
__global__ void k_scan1() {
    int s = blockIdx.x / SCAN_NB;
    int blk = blockIdx.x % SCAN_NB;
    int i = blk * SCAN_B + threadIdx.x;
    int val = (i < NMAX) ? g_deg[s][i] : 0;
    __shared__ int sm[SCAN_B];
    sm[threadIdx.x] = val;
    __syncthreads();
#pragma unroll
    for (int off = 1; off < SCAN_B; off <<= 1) {
        int t = (threadIdx.x >= off) ? sm[threadIdx.x - off] : 0;
        __syncthreads();
        sm[threadIdx.x] += t;
        __syncthreads();
    }
    if (i < NMAX) g_rowptr[s][i] = sm[threadIdx.x] - val;
    if (threadIdx.x == SCAN_B - 1) g_bsum[s][blk] = sm[threadIdx.x];
}

// scan pass 2: scan block totals (one block per graph)
__global__ void k_scan2() {
    int s = blockIdx.x;
    __shared__ int sm[256];
    int val = (threadIdx.x < SCAN_NB) ? g_bsum[s][threadIdx.x] : 0;
    sm[threadIdx.x] = val;
    __syncthreads();
#pragma unroll
    for (int off = 1; off < 256; off <<= 1) {
        int t = (threadIdx.x >= off) ? sm[threadIdx.x - off] : 0;
        __syncthreads();
        sm[threadIdx.x] += t;
        __syncthreads();
    }
    if (threadIdx.x < SCAN_NB) g_boff[s][threadIdx.x] = sm[threadIdx.x] - val;
}

// scan pass 3: add block offsets, init cursor
__global__ void k_scan3() {
    int t = blockIdx.x * blockDim.x + threadIdx.x;
    if (t >= 2 * NMAX) return;
    int s = t >= NMAX; int i = t - s * NMAX;
    int r = g_rowptr[s][i] + g_boff[s][i / SCAN_B];
    g_rowptr[s][i] = r;
    g_cursor[s][i] = r;
}

// CSR fill: csr[slot of dst] = src
__global__ void k_fill(const int* __restrict__ eA, const int* __restrict__ eC) {
    int t = blockIdx.x * blockDim.x + threadIdx.x;
    if (t >= 2 * EMAX) return;
    int s = t >= EMAX; int e = t - s * EMAX;
    const int* edge = s ? eC : eA;
    int u = __ldg(edge + e);
    int v = __ldg(edge + EMAX + e);
    int slot = atomicAdd(&g_cursor[s][v], 1);
    g_csr[s][slot] = u;
}

// layer-1 node init: dinv, hh1 = tab[type] * dinv
__global__ void k_node1(const int* __restrict__ typeA, const int* __restrict__ typeC) {
    int t = blockIdx.x * blockDim.x + threadIdx.x;
    int grp = t >> 4, lane = t & 15;
    if (grp >= 2 * NMAX) return;
    int s = grp >= NMAX; int v = grp - s * NMAX;
    float dv = rsqrtf((float)g_deg[s][v] + 1.0f);
    if (lane == 0) g_dinv[s][v] = dv;
    int ty = __ldg((s ? typeC : typeA) + v);
    float4 w = ((const float4*)g_tab[s])[ty * 16 + lane];
    g_h[s][v * 16 + lane] = make_float4(w.x * dv, w.y * dv, w.z * dv, w.w * dv);
}

// pull layer 1: x = relu(dinv[v] * (sum hh1[neighbors] + hh1[v]) + b1)
__global__ void __launch_bounds__(256) k_pull1(const float* __restrict__ b1A,
                                               const float* __restrict__ b1C) {
    int t = blockIdx.x * blockDim.x + threadIdx.x;
    int grp = t >> 4, lane = t & 15;
    if (grp >= 2 * NMAX) return;
    int s = grp >= NMAX; int v = grp - s * NMAX;
    const float4* __restrict__ hh = g_h[s];
    int r = g_rowptr[s][v], d = g_deg[s][v];
    const int* __restrict__ cs = g_csr[s] + r;
    float4 acc = hh[v * 16 + lane];
    int k = 0;
    for (; k + 4 <= d; k += 4) {
        int i0 = __ldg(cs + k), i1 = __ldg(cs + k + 1);
        int i2 = __ldg(cs + k + 2), i3 = __ldg(cs + k + 3);
        float4 a0 = hh[i0 * 16 + lane];
        float4 a1 = hh[i1 * 16 + lane];
        float4 a2 = hh[i2 * 16 + lane];
        float4 a3 = hh[i3 * 16 + lane];
        acc.x += (a0.x + a1.x) + (a2.x + a3.x);
        acc.y += (a0.y + a1.y) + (a2.y + a3.y);
        acc.z += (a0.z + a1.z) + (a2.z + a3.z);
        acc.w += (a0.w + a1.w) + (a2.w + a3.w);
    }
    for (; k < d; k++) {
        int i0 = __ldg(cs + k);
        float4 a = hh[i0 * 16 + lane];
        acc.x += a.x; acc.y += a.y; acc.z += a.z; acc.w += a.w;
    }
    float dv = g_dinv[s][v];
    float4 bv = ((const float4*)(s ? b1C : b1A))[lane];
    float4 x;
    x.x = fmaxf(fmaf(dv, acc.x, bv.x), 0.f);
    x.y = fmaxf(fmaf(dv, acc.y, bv.y), 0.f);
    x.z = fmaxf(fmaf(dv, acc.z, bv.z), 0.f);
    x.w = fmaxf(fmaf(dv, acc.w, bv.w), 0.f);
    g_agg[s][v * 16 + lane] = x;
}

// layer-2 GEMV: hh2 = (x @ W2) * dinv   (W2 column per thread in regs)
__global__ void k_gemv2(const float* __restrict__ WA, const float* __restrict__ WC, int n_half) {
    int s = blockIdx.x >= n_half;
    int blk = blockIdx.x - s * n_half;
    const float* W = s ? WC : WA;
    int j = threadIdx.x & 63;
    int sub = threadIdx.x >> 6;   // 0..3
    __shared__ float sx[4][64];
    float wcol[64];
#pragma unroll
    for (int k = 0; k < 64; k++) wcol[k] = W[k * 64 + j];
    const float* xin = (const float*)g_agg[s];
    float* hh = (float*)g_h[s];
    for (int base = blk * 4; base < NMAX; base += n_half * 4) {
        int node = base + sub;
        float xv = (node < NMAX) ? xin[node * 64 + j] : 0.f;
        sx[sub][j] = xv;
        __syncthreads();
        if (node < NMAX) {
            float acc = 0.f;
#pragma unroll
            for (int k = 0; k < 64; k++) acc = fmaf(sx[sub][k], wcol[k], acc);
            hh[node * 64 + j] = acc * g_dinv[s][node];
        }
        __syncthreads();
    }
}

// pull layer 2 + pool: pool[batch[v]] += dinv[v]*(sum hh2 + hh2[v]) + b2
__global__ void __launch_bounds__(256) k_pull2(const int* __restrict__ batchA,
                                               const int* __restrict__ batchC,
                                               const float* __restrict__ b2A,
                                               const float* __restrict__ b2C) {
    int t = blockIdx.x * blockDim.x + threadIdx.x;
    int grp = t >> 4, lane = t & 15;
    if (grp >= 2 * NMAX) return;
    int s = grp >= NMAX; int v = grp - s * NMAX;
    const float4* __restrict__ hh = g_h[s];
    int r = g_rowptr[s][v], d = g_deg[s][v];
    const int* __restrict__ cs = g_csr[s] + r;
    float4 acc = hh[v * 16 + lane];
    int k = 0;
    for (; k + 4 <= d; k += 4) {
        int i0 = __ldg(cs + k), i1 = __ldg(cs + k + 1);
        int i2 = __ldg(cs + k + 2), i3 = __ldg(cs + k + 3);
        float4 a0 = hh[i0 * 16 + lane];
        float4 a1 = hh[i1 * 16 + lane];
        float4 a2 = hh[i2 * 16 + lane];
        float4 a3 = hh[i3 * 16 + lane];
        acc.x += (a0.x + a1.x) + (a2.x + a3.x);
        acc.y += (a0.y + a1.y) + (a2.y + a3.y);
        acc.z += (a0.z + a1.z) + (a2.z + a3.z);
        acc.w += (a0.w + a1.w) + (a2.w + a3.w);
    }
    for (; k < d; k++) {
        int i0 = __ldg(cs + k);
        float4 a = hh[i0 * 16 + lane];
        acc.x += a.x; acc.y += a.y; acc.z += a.z; acc.w += a.w;
    }
    float dv = g_dinv[s][v];
    float4 bv = ((const float4*)(s ? b2C : b2A))[lane];
    float4 val;
    val.x = fmaf(dv, acc.x, bv.x);
    val.y = fmaf(dv, acc.y, bv.y);
    val.z = fmaf(dv, acc.z, bv.z);
    val.w = fmaf(dv, acc.w, bv.w);
    int g = __ldg((s ? batchC : batchA) + v);
    red_add_v4((float*)&g_pool[s][g * 16 + lane], val);
}

// fused epilogue: gate1, sem proj, gate2, layernorm, classifier. 1 block/graph.
__global__ void k_epilogue(const float* __restrict__ sem,
                           const float* __restrict__ Wg1, const float* __restrict__ bg1,
                           const float* __restrict__ Wsem, const float* __restrict__ bsem,
                           const float* __restrict__ Wg2, const float* __restrict__ bg2,
                           const float* __restrict__ ln_g, const float* __restrict__ ln_b,
                           const float* __restrict__ Wc, const float* __restrict__ bc,
                           float* __restrict__ out) {
    int g = blockIdx.x, j = threadIdx.x;  // 64 threads
    __shared__ float sa[64], sb[64], hs[64], hm[64];
    __shared__ float ssem[SEM];
    __shared__ float2 rbuf[64];

    float a = ((const float*)g_pool[0])[g * 64 + j];
    float b = ((const float*)g_pool[1])[g * 64 + j];
    sa[j] = a; sb[j] = b;
    for (int t = j; t < SEM; t += 64) ssem[t] = sem[g * SEM + t];
    __syncthreads();

    float acc = bg1[j];
#pragma unroll
    for (int k = 0; k < 64; k++) acc = fmaf(sa[k], Wg1[k * 64 + j], acc);
#pragma unroll
    for (int k = 0; k < 64; k++) acc = fmaf(sb[k], Wg1[(64 + k) * 64 + j], acc);
    float g1 = 1.f / (1.f + expf(-acc));
    float hstruct = g1 * a + (1.f - g1) * b;

    float acc2 = bsem[j];
#pragma unroll 8
    for (int k = 0; k < SEM; k++) acc2 = fmaf(ssem[k], Wsem[k * 64 + j], acc2);
    float hsem = fmaxf(acc2, 0.f);

    hs[j] = hstruct; hm[j] = hsem;
    __syncthreads();

    float acc3 = bg2[j];
#pragma unroll
    for (int k = 0; k < 64; k++) acc3 = fmaf(hs[k], Wg2[k * 64 + j], acc3);
#pragma unroll
    for (int k = 0; k < 64; k++) acc3 = fmaf(hm[k], Wg2[(64 + k) * 64 + j], acc3);
    float g2 = 1.f / (1.f + expf(-acc3));
    float h = g2 * hstruct + (1.f - g2) * hsem;

    rbuf[j] = make_float2(h, h * h);
    __syncthreads();
    for (int off = 32; off > 0; off >>= 1) {
        if (j < off) { rbuf[j].x += rbuf[j + off].x; rbuf[j].y += rbuf[j + off].y; }
        __syncthreads();
    }
    float mu  = rbuf[0].x * (1.f / 64.f);
    float var = rbuf[0].y * (1.f / 64.f) - mu * mu;
    float hn = (h - mu) * rsqrtf(var + 1e-5f) * ln_g[j] + ln_b[j];
    __syncthreads();

    rbuf[j] = make_float2(hn * Wc[j * 2 + 0], hn * Wc[j * 2 + 1]);
    __syncthreads();
    for (int off = 32; off > 0; off >>= 1) {
        if (j < off) { rbuf[j].x += rbuf[j + off].x; rbuf[j].y += rbuf[j + off].y; }
        __syncthreads();
    }
    if (j == 0) {
        out[g * 2 + 0] = rbuf[0].x + bc[0];
        out[g * 2 + 1] = rbuf[0].y + bc[1];
    }
}

// ---------------- launch ----------------
extern "C" void kernel_launch(void* const* d_in, const int* in_sizes, int n_in,
                              void* d_out, int out_size) {
    const int*   ast_type  = (const int*)  d_in[0];
    const int*   ast_edge  = (const int*)  d_in[1];
    const int*   ast_batch = (const int*)  d_in[2];
    const int*   cfg_type  = (const int*)  d_in[3];
    const int*   cfg_edge  = (const int*)  d_in[4];
    const int*   cfg_batch = (const int*)  d_in[5];
    const float* sem       = (const float*)d_in[6];
    const float* ast_emb   = (const float*)d_in[7];
    const float* cfg_emb   = (const float*)d_in[8];
    const float* ast_W1    = (const float*)d_in[9];
    const float* ast_b1    = (const float*)d_in[10];
    const float* ast_W2    = (const float*)d_in[11];
    const float* ast_b2    = (const float*)d_in[12];
    const float* cfg_W1    = (const float*)d_in[13];
    const float* cfg_b1    = (const float*)d_in[14];
    const float* cfg_W2    = (const float*)d_in[15];
    const float* cfg_b2    = (const float*)d_in[16];
    const float* Wg1       = (const float*)d_in[17];
    const float* bg1       = (const float*)d_in[18];
    const float* Wsem      = (const float*)d_in[19];
    const float* bsem      = (const float*)d_in[20];
    const float* Wg2       = (const float*)d_in[21];
    const float* bg2       = (const float*)d_in[22];
    const float* ln_g      = (const float*)d_in[23];
    const float* ln_b      = (const float*)d_in[24];
    const float* Wc        = (const float*)d_in[25];
    const float* bc        = (const float*)d_in[26];
    float* out = (float*)d_out;

    k_zero<<<(NMAX + 255) / 256, 256>>>();
    k_table<<<300, 64>>>(ast_emb, ast_W1, cfg_emb, cfg_W1);

    k_deg<<<(2 * EMAX + 255) / 256, 256>>>(ast_edge, cfg_edge);
    k_scan1<<<2 * SCAN_NB, SCAN_B>>>();
    k_scan2<<<2, 256>>>();
    k_scan3<<<(2 * NMAX + 255) / 256, 256>>>();
    k_fill<<<(2 * EMAX + 255) / 256, 256>>>(ast_edge, cfg_edge);

    k_node1<<<(2 * NMAX * 16 + 255) / 256, 256>>>(ast_type, cfg_type);
    k_pull1<<<(2 * NMAX * 16 + 255) / 256, 256>>>(ast_b1, cfg_b1);
    k_gemv2<<<4096, 256>>>(ast_W2, cfg_W2, 2048);
    k_pull2<<<(2 * NMAX * 16 + 255) / 256, 256>>>(ast_batch, cfg_batch, ast_b2, cfg_b2);

    k_epilogue<<<NG, 64>>>(sem, Wg1, bg1, Wsem, bsem, Wg2, bg2,
                           ln_g, ln_b, Wc, bc, out);
}

// round 5
// speedup vs baseline: 1.8063x; 1.1802x over previous
#include <cuda_runtime.h>
#include <cuda_bf16.h>
#include <math.h>

#define NG 1024
#define SEM 768
#define NMAX 100000
#define EMAX 1250000
#define SCAN_B 512
#define SCAN_NB 196   // ceil(100000/512)

// ---------------- device scratch (static, allocation-free) ----------------
__device__ int    g_deg   [2][NMAX];
__device__ int    g_rowptr[2][NMAX];
__device__ int    g_cursor[2][NMAX];
__device__ int    g_bsum  [2][SCAN_NB];
__device__ int    g_boff  [2][SCAN_NB];
__device__ int    g_csr   [2][EMAX];
__device__ int2   g_nd    [2][NMAX];      // {type, dinv as bits}
__device__ float4 g_x     [2][NMAX * 16]; // xd = dinv * relu(layer1)  (64 f/node)
__device__ float4 g_pool  [2][NG * 16];
__device__ float  g_cnt   [2][NG];
__device__ float  g_tab   [2][200 * 64];  // emb @ W1 lookup table

__device__ __forceinline__ void red_add_v4(float* addr, float4 v) {
    asm volatile("red.global.add.v4.f32 [%0], {%1, %2, %3, %4};"
                 :: "l"(addr), "f"(v.x), "f"(v.y), "f"(v.z), "f"(v.w)
                 : "memory");
}
__device__ __forceinline__ float4 ldg4(const float* p) {
    return __ldg((const float4*)p);
}

// ---------------- kernels ----------------

__global__ void k_zero() {
    int i = blockIdx.x * blockDim.x + threadIdx.x;
    if (i < NMAX) { g_deg[0][i] = 0; g_deg[1][i] = 0; }
    if (i < NG * 16) {
        g_pool[0][i] = make_float4(0.f, 0.f, 0.f, 0.f);
        g_pool[1][i] = make_float4(0.f, 0.f, 0.f, 0.f);
    }
    if (i < NG) { g_cnt[0][i] = 0.f; g_cnt[1][i] = 0.f; }
}

// tab[s] = emb @ W1  (200 rows ast, 100 rows cfg)
__global__ void k_table(const float* __restrict__ embA, const float* __restrict__ W1A,
                        const float* __restrict__ embC, const float* __restrict__ W1C) {
    __shared__ float sx[64];
    int r = blockIdx.x, j = threadIdx.x;
    const float* emb; const float* W; float* tab; int row;
    if (r < 200) { emb = embA; W = W1A; tab = g_tab[0]; row = r; }
    else         { emb = embC; W = W1C; tab = g_tab[1]; row = r - 200; }
    sx[j] = emb[row * 64 + j];
    __syncthreads();
    float acc = 0.f;
#pragma unroll
    for (int k = 0; k < 64; k++) acc = fmaf(sx[k], W[k * 64 + j], acc);
    tab[row * 64 + j] = acc;
}

// in-degree counts over dst, both graphs in one launch
__global__ void k_deg(const int* __restrict__ eA, const int* __restrict__ eC) {
    int t = blockIdx.x * blockDim.x + threadIdx.x;
    if (t >= 2 * EMAX) return;
    int s = t >= EMAX; int e = t - s * EMAX;
    const int* edge = s ? eC : eA;
    atomicAdd(&g_deg[s][__ldg(edge + EMAX + e)], 1);
}

// scan pass 1: per-block exclusive scan of deg -> rowptr (local), block totals
__global__ void k_scan1() {
    int s = blockIdx.x / SCAN_NB;
    int blk = blockIdx.x % SCAN_NB;
    int i = blk * SCAN_B + threadIdx.x;
    int val = (i < NMAX) ? g_deg[s][i] : 0;
    __shared__ int sm[SCAN_B];
    sm[threadIdx.x] = val;
    __syncthreads();
#pragma unroll
    for (int off = 1; off < SCAN_B; off <<= 1) {
        int t = (threadIdx.x >= off) ? sm[threadIdx.x - off] : 0;
        __syncthreads();
        sm[threadIdx.x] += t;
        __syncthreads();
    }
    if (i < NMAX) g_rowptr[s][i] = sm[threadIdx.x] - val;
    if (threadIdx.x == SCAN_B - 1) g_bsum[s][blk] = sm[threadIdx.x];
}

// scan pass 2: scan block totals (one block per graph)
__global__ void k_scan2() {
    int s = blockIdx.x;
    __shared__ int sm[256];
    int val = (threadIdx.x < SCAN_NB) ? g_bsum[s][threadIdx.x] : 0;
    sm[threadIdx.x] = val;
    __syncthreads();
#pragma unroll
    for (int off = 1; off < 256; off <<= 1) {
        int t = (threadIdx.x >= off) ? sm[threadIdx.x - off] : 0;
        __syncthreads();
        sm[threadIdx.x] += t;
        __syncthreads();
    }
    if (threadIdx.x < SCAN_NB) g_boff[s][threadIdx.x] = sm[threadIdx.x] - val;
}

// scan pass 3: finalize rowptr/cursor + node init (dinv + packed {type,dinv})
__global__ void k_scan3(const int* __restrict__ tyA, const int* __restrict__ tyC) {
    int t = blockIdx.x * blockDim.x + threadIdx.x;
    if (t >= 2 * NMAX) return;
    int s = t >= NMAX; int i = t - s * NMAX;
    int r = g_rowptr[s][i] + g_boff[s][i / SCAN_B];
    g_rowptr[s][i] = r;
    g_cursor[s][i] = r;
    float dv = rsqrtf((float)g_deg[s][i] + 1.0f);
    int ty = __ldg((s ? tyC : tyA) + i);
    g_nd[s][i] = make_int2(ty, __float_as_int(dv));
}

// CSR fill: csr[slot of dst] = src
__global__ void k_fill(const int* __restrict__ eA, const int* __restrict__ eC) {
    int t = blockIdx.x * blockDim.x + threadIdx.x;
    if (t >= 2 * EMAX) return;
    int s = t >= EMAX; int e = t - s * EMAX;
    const int* edge = s ? eC : eA;
    int u = __ldg(edge + e);
    int v = __ldg(edge + EMAX + e);
    int slot = atomicAdd(&g_cursor[s][v], 1);
    g_csr[s][slot] = u;
}

// pull layer 1 (table-based):
// xd_v = dinv_v * relu( dinv_v*(sum_u tab[ty_u]*dinv_u + tab[ty_v]*dinv_v) + b1 )
__global__ void __launch_bounds__(256) k_pull1(const float* __restrict__ b1A,
                                               const float* __restrict__ b1C) {
    int t = blockIdx.x * blockDim.x + threadIdx.x;
    int grp = t >> 4, lane = t & 15;
    if (grp >= 2 * NMAX) return;
    int s = grp >= NMAX; int v = grp - s * NMAX;
    const float4* __restrict__ tab4 = (const float4*)g_tab[s];
    const int2* __restrict__ nd = g_nd[s];

    int2 ndv = __ldg(&nd[v]);
    float dv = __int_as_float(ndv.y);
    float4 tv = tab4[ndv.x * 16 + lane];
    float4 acc = make_float4(tv.x * dv, tv.y * dv, tv.z * dv, tv.w * dv);

    int r = g_rowptr[s][v], d = g_deg[s][v];
    const int* __restrict__ cs = g_csr[s] + r;
    int k = 0;
    for (; k + 4 <= d; k += 4) {
        int i0 = __ldg(cs + k), i1 = __ldg(cs + k + 1);
        int i2 = __ldg(cs + k + 2), i3 = __ldg(cs + k + 3);
        int2 n0 = __ldg(&nd[i0]), n1 = __ldg(&nd[i1]);
        int2 n2 = __ldg(&nd[i2]), n3 = __ldg(&nd[i3]);
        float d0 = __int_as_float(n0.y), d1 = __int_as_float(n1.y);
        float d2 = __int_as_float(n2.y), d3 = __int_as_float(n3.y);
        float4 t0 = tab4[n0.x * 16 + lane];
        float4 t1 = tab4[n1.x * 16 + lane];
        float4 t2 = tab4[n2.x * 16 + lane];
        float4 t3 = tab4[n3.x * 16 + lane];
        acc.x = fmaf(t0.x, d0, acc.x); acc.y = fmaf(t0.y, d0, acc.y);
        acc.z = fmaf(t0.z, d0, acc.z); acc.w = fmaf(t0.w, d0, acc.w);
        acc.x = fmaf(t1.x, d1, acc.x); acc.y = fmaf(t1.y, d1, acc.y);
        acc.z = fmaf(t1.z, d1, acc.z); acc.w = fmaf(t1.w, d1, acc.w);
        acc.x = fmaf(t2.x, d2, acc.x); acc.y = fmaf(t2.y, d2, acc.y);
        acc.z = fmaf(t2.z, d2, acc.z); acc.w = fmaf(t2.w, d2, acc.w);
        acc.x = fmaf(t3.x, d3, acc.x); acc.y = fmaf(t3.y, d3, acc.y);
        acc.z = fmaf(t3.z, d3, acc.z); acc.w = fmaf(t3.w, d3, acc.w);
    }
    for (; k < d; k++) {
        int i0 = __ldg(cs + k);
        int2 n0 = __ldg(&nd[i0]);
        float d0 = __int_as_float(n0.y);
        float4 t0 = tab4[n0.x * 16 + lane];
        acc.x = fmaf(t0.x, d0, acc.x); acc.y = fmaf(t0.y, d0, acc.y);
        acc.z = fmaf(t0.z, d0, acc.z); acc.w = fmaf(t0.w, d0, acc.w);
    }
    float4 bv = ldg4((s ? b1C : b1A) + lane * 4);
    float4 xd;
    xd.x = dv * fmaxf(fmaf(dv, acc.x, bv.x), 0.f);
    xd.y = dv * fmaxf(fmaf(dv, acc.y, bv.y), 0.f);
    xd.z = dv * fmaxf(fmaf(dv, acc.z, bv.z), 0.f);
    xd.w = dv * fmaxf(fmaf(dv, acc.w, bv.w), 0.f);
    g_x[s][v * 16 + lane] = xd;
}

// pull layer 2 + pool (pre-GEMM):
// pool[batch_v] += dinv_v * (sum_u xd_u + xd_v);  cnt[batch_v] += 1
__global__ void __launch_bounds__(256) k_pull2(const int* __restrict__ batchA,
                                               const int* __restrict__ batchC) {
    int t = blockIdx.x * blockDim.x + threadIdx.x;
    int grp = t >> 4, lane = t & 15;
    if (grp >= 2 * NMAX) return;
    int s = grp >= NMAX; int v = grp - s * NMAX;
    const float4* __restrict__ xd = g_x[s];

    float4 acc = xd[v * 16 + lane];
    int r = g_rowptr[s][v], d = g_deg[s][v];
    const int* __restrict__ cs = g_csr[s] + r;
    int k = 0;
    for (; k + 4 <= d; k += 4) {
        int i0 = __ldg(cs + k), i1 = __ldg(cs + k + 1);
        int i2 = __ldg(cs + k + 2), i3 = __ldg(cs + k + 3);
        float4 a0 = xd[i0 * 16 + lane];
        float4 a1 = xd[i1 * 16 + lane];
        float4 a2 = xd[i2 * 16 + lane];
        float4 a3 = xd[i3 * 16 + lane];
        acc.x += (a0.x + a1.x) + (a2.x + a3.x);
        acc.y += (a0.y + a1.y) + (a2.y + a3.y);
        acc.z += (a0.z + a1.z) + (a2.z + a3.z);
        acc.w += (a0.w + a1.w) + (a2.w + a3.w);
    }
    for (; k < d; k++) {
        int i0 = __ldg(cs + k);
        float4 a = xd[i0 * 16 + lane];
        acc.x += a.x; acc.y += a.y; acc.z += a.z; acc.w += a.w;
    }
    float dv = __int_as_float(__ldg(&g_nd[s][v]).y);
    float4 val = make_float4(dv * acc.x, dv * acc.y, dv * acc.z, dv * acc.w);
    int g = __ldg((s ? batchC : batchA) + v);
    red_add_v4((float*)&g_pool[s][g * 16 + lane], val);
    if (lane == 0) atomicAdd(&g_cnt[s][g], 1.0f);
}

// epilogue v2: 128 blocks x 128 thr; 8 graphs/block; 16 lanes x 4 cols per graph.
// per graph: a = P_ast@W2A + cntA*b2A ; b = P_cfg@W2C + cntC*b2C ; gates ; sem ;
// layernorm ; classifier.
__global__ void __launch_bounds__(128) k_epilogue(
    const float* __restrict__ sem,
    const float* __restrict__ W2A, const float* __restrict__ b2A,
    const float* __restrict__ W2C, const float* __restrict__ b2C,
    const float* __restrict__ Wg1, const float* __restrict__ bg1,
    const float* __restrict__ Wsem, const float* __restrict__ bsem,
    const float* __restrict__ Wg2, const float* __restrict__ bg2,
    const float* __restrict__ ln_g, const float* __restrict__ ln_b,
    const float* __restrict__ Wc, const float* __restrict__ bc,
    float* __restrict__ out) {
    int sg = threadIdx.x >> 4;     // subgroup 0..7 (one graph each)
    int l  = threadIdx.x & 15;
    int g  = blockIdx.x * 8 + sg;
    int j0 = l * 4;

    __shared__ float sPA[8][64], sPC[8][64];
    __shared__ float sA [8][64], sB [8][64];
    __shared__ float sHS[8][64], sHM[8][64];

    float4 PA = g_pool[0][g * 16 + l];
    float4 PC = g_pool[1][g * 16 + l];
    *(float4*)&sPA[sg][j0] = PA;
    *(float4*)&sPC[sg][j0] = PC;
    float cntA = g_cnt[0][g], cntC = g_cnt[1][g];
    __syncwarp();

    // W2 GEMV (64x64 each)
    float4 a = make_float4(0.f, 0.f, 0.f, 0.f);
    float4 b = make_float4(0.f, 0.f, 0.f, 0.f);
#pragma unroll 4
    for (int k = 0; k < 64; k++) {
        float pa = sPA[sg][k], pc = sPC[sg][k];
        float4 wa = ldg4(W2A + k * 64 + j0);
        float4 wc = ldg4(W2C + k * 64 + j0);
        a.x = fmaf(pa, wa.x, a.x); a.y = fmaf(pa, wa.y, a.y);
        a.z = fmaf(pa, wa.z, a.z); a.w = fmaf(pa, wa.w, a.w);
        b.x = fmaf(pc, wc.x, b.x); b.y = fmaf(pc, wc.y, b.y);
        b.z = fmaf(pc, wc.z, b.z); b.w = fmaf(pc, wc.w, b.w);
    }
    {
        float4 ba = ldg4(b2A + j0), bb = ldg4(b2C + j0);
        a.x = fmaf(cntA, ba.x, a.x); a.y = fmaf(cntA, ba.y, a.y);
        a.z = fmaf(cntA, ba.z, a.z); a.w = fmaf(cntA, ba.w, a.w);
        b.x = fmaf(cntC, bb.x, b.x); b.y = fmaf(cntC, bb.y, b.y);
        b.z = fmaf(cntC, bb.z, b.z); b.w = fmaf(cntC, bb.w, b.w);
    }
    *(float4*)&sA[sg][j0] = a;
    *(float4*)&sB[sg][j0] = b;
    __syncwarp();

    // gate 1
    float4 acc = ldg4(bg1 + j0);
#pragma unroll 4
    for (int k = 0; k < 64; k++) {
        float va = sA[sg][k];
        float4 w = ldg4(Wg1 + k * 64 + j0);
        acc.x = fmaf(va, w.x, acc.x); acc.y = fmaf(va, w.y, acc.y);
        acc.z = fmaf(va, w.z, acc.z); acc.w = fmaf(va, w.w, acc.w);
    }
#pragma unroll 4
    for (int k = 0; k < 64; k++) {
        float vb = sB[sg][k];
        float4 w = ldg4(Wg1 + (64 + k) * 64 + j0);
        acc.x = fmaf(vb, w.x, acc.x); acc.y = fmaf(vb, w.y, acc.y);
        acc.z = fmaf(vb, w.z, acc.z); acc.w = fmaf(vb, w.w, acc.w);
    }
    float4 g1;
    g1.x = 1.f / (1.f + expf(-acc.x));
    g1.y = 1.f / (1.f + expf(-acc.y));
    g1.z = 1.f / (1.f + expf(-acc.z));
    g1.w = 1.f / (1.f + expf(-acc.w));
    float4 hst;
    hst.x = g1.x * a.x + (1.f - g1.x) * b.x;
    hst.y = g1.y * a.y + (1.f - g1.y) * b.y;
    hst.z = g1.z * a.z + (1.f - g1.z) * b.z;
    hst.w = g1.w * a.w + (1.f - g1.w) * b.w;

    // sem projection
    float4 ac2 = ldg4(bsem + j0);
    const float* semrow = sem + g * SEM;
#pragma unroll 4
    for (int k = 0; k < SEM; k += 4) {
        float4 s4 = ldg4(semrow + k);
        float4 w0 = ldg4(Wsem + (k + 0) * 64 + j0);
        float4 w1 = ldg4(Wsem + (k + 1) * 64 + j0);
        float4 w2 = ldg4(Wsem + (k + 2) * 64 + j0);
        float4 w3 = ldg4(Wsem + (k + 3) * 64 + j0);
        ac2.x = fmaf(s4.x, w0.x, ac2.x); ac2.y = fmaf(s4.x, w0.y, ac2.y);
        ac2.z = fmaf(s4.x, w0.z, ac2.z); ac2.w = fmaf(s4.x, w0.w, ac2.w);
        ac2.x = fmaf(s4.y, w1.x, ac2.x); ac2.y = fmaf(s4.y, w1.y, ac2.y);
        ac2.z = fmaf(s4.y, w1.z, ac2.z); ac2.w = fmaf(s4.y, w1.w, ac2.w);
        ac2.x = fmaf(s4.z, w2.x, ac2.x); ac2.y = fmaf(s4.z, w2.y, ac2.y);
        ac2.z = fmaf(s4.z, w2.z, ac2.z); ac2.w = fmaf(s4.z, w2.w, ac2.w);
        ac2.x = fmaf(s4.w, w3.x, ac2.x); ac2.y = fmaf(s4.w, w3.y, ac2.y);
        ac2.z = fmaf(s4.w, w3.z, ac2.z); ac2.w = fmaf(s4.w, w3.w, ac2.w);
    }
    float4 hm;
    hm.x = fmaxf(ac2.x, 0.f); hm.y = fmaxf(ac2.y, 0.f);
    hm.z = fmaxf(ac2.z, 0.f); hm.w = fmaxf(ac2.w, 0.f);

    *(float4*)&sHS[sg][j0] = hst;
    *(float4*)&sHM[sg][j0] = hm;
    __syncwarp();

    // gate 2
    float4 ac3 = ldg4(bg2 + j0);
#pragma unroll 4
    for (int k = 0; k < 64; k++) {
        float vh = sHS[sg][k];
        float4 w = ldg4(Wg2 + k * 64 + j0);
        ac3.x = fmaf(vh, w.x, ac3.x); ac3.y = fmaf(vh, w.y, ac3.y);
        ac3.z = fmaf(vh, w.z, ac3.z); ac3.w = fmaf(vh, w.w, ac3.w);
    }
#pragma unroll 4
    for (int k = 0; k < 64; k++) {
        float vm = sHM[sg][k];
        float4 w = ldg4(Wg2 + (64 + k) * 64 + j0);
        ac3.x = fmaf(vm, w.x, ac3.x); ac3.y = fmaf(vm, w.y, ac3.y);
        ac3.z = fmaf(vm, w.z, ac3.z); ac3.w = fmaf(vm, w.w, ac3.w);
    }
    float4 g2;
    g2.x = 1.f / (1.f + expf(-ac3.x));
    g2.y = 1.f / (1.f + expf(-ac3.y));
    g2.z = 1.f / (1.f + expf(-ac3.z));
    g2.w = 1.f / (1.f + expf(-ac3.w));
    float4 h;
    h.x = g2.x * hst.x + (1.f - g2.x) * hm.x;
    h.y = g2.y * hst.y + (1.f - g2.y) * hm.y;
    h.z = g2.z * hst.z + (1.f - g2.z) * hm.z;
    h.w = g2.w * hst.w + (1.f - g2.w) * hm.w;

    // layernorm over 64 (16-lane shfl reduce, each lane holds 4)
    float s1 = (h.x + h.y) + (h.z + h.w);
    float s2 = (h.x * h.x + h.y * h.y) + (h.z * h.z + h.w * h.w);
#pragma unroll
    for (int m = 1; m < 16; m <<= 1) {
        s1 += __shfl_xor_sync(0xFFFFFFFFu, s1, m);
        s2 += __shfl_xor_sync(0xFFFFFFFFu, s2, m);
    }
    float mu  = s1 * (1.f / 64.f);
    float var = s2 * (1.f / 64.f) - mu * mu;
    float rstd = rsqrtf(var + 1e-5f);
    float4 lg = ldg4(ln_g + j0), lb = ldg4(ln_b + j0);
    float4 hn;
    hn.x = (h.x - mu) * rstd * lg.x + lb.x;
    hn.y = (h.y - mu) * rstd * lg.y + lb.y;
    hn.z = (h.z - mu) * rstd * lg.z + lb.z;
    hn.w = (h.w - mu) * rstd * lg.w + lb.w;

    // classifier (NCLS=2): Wc is [64,2]
    float4 wc0 = ldg4(Wc + j0 * 2);       // {Wc[j0][0],Wc[j0][1],Wc[j0+1][0],Wc[j0+1][1]}
    float4 wc1 = ldg4(Wc + j0 * 2 + 4);
    float o0 = hn.x * wc0.x + hn.y * wc0.z + hn.z * wc1.x + hn.w * wc1.z;
    float o1 = hn.x * wc0.y + hn.y * wc0.w + hn.z * wc1.y + hn.w * wc1.w;
#pragma unroll
    for (int m = 1; m < 16; m <<= 1) {
        o0 += __shfl_xor_sync(0xFFFFFFFFu, o0, m);
        o1 += __shfl_xor_sync(0xFFFFFFFFu, o1, m);
    }
    if (l == 0) {
        out[g * 2 + 0] = o0 + __ldg(bc + 0);
        out[g * 2 + 1] = o1 + __ldg(bc + 1);
    }
}

// ---------------- launch ----------------
extern "C" void kernel_launch(void* const* d_in, const int* in_sizes, int n_in,
                              void* d_out, int out_size) {
    const int*   ast_type  = (const int*)  d_in[0];
    const int*   ast_edge  = (const int*)  d_in[1];
    const int*   ast_batch = (const int*)  d_in[2];
    const int*   cfg_type  = (const int*)  d_in[3];
    const int*   cfg_edge  = (const int*)  d_in[4];
    const int*   cfg_batch = (const int*)  d_in[5];
    const float* sem       = (const float*)d_in[6];
    const float* ast_emb   = (const float*)d_in[7];
    const float* cfg_emb   = (const float*)d_in[8];
    const float* ast_W1    = (const float*)d_in[9];
    const float* ast_b1    = (const float*)d_in[10];
    const float* ast_W2    = (const float*)d_in[11];
    const float* ast_b2    = (const float*)d_in[12];
    const float* cfg_W1    = (const float*)d_in[13];
    const float* cfg_b1    = (const float*)d_in[14];
    const float* cfg_W2    = (const float*)d_in[15];
    const float* cfg_b2    = (const float*)d_in[16];
    const float* Wg1       = (const float*)d_in[17];
    const float* bg1       = (const float*)d_in[18];
    const float* Wsem      = (const float*)d_in[19];
    const float* bsem      = (const float*)d_in[20];
    const float* Wg2       = (const float*)d_in[21];
    const float* bg2       = (const float*)d_in[22];
    const float* ln_g      = (const float*)d_in[23];
    const float* ln_b      = (const float*)d_in[24];
    const float* Wc        = (const float*)d_in[25];
    const float* bc        = (const float*)d_in[26];
    float* out = (float*)d_out;

    k_zero<<<(NMAX + 255) / 256, 256>>>();
    k_table<<<300, 64>>>(ast_emb, ast_W1, cfg_emb, cfg_W1);

    k_deg<<<(2 * EMAX + 255) / 256, 256>>>(ast_edge, cfg_edge);
    k_scan1<<<2 * SCAN_NB, SCAN_B>>>();
    k_scan2<<<2, 256>>>();
    k_scan3<<<(2 * NMAX + 255) / 256, 256>>>(ast_type, cfg_type);
    k_fill<<<(2 * EMAX + 255) / 256, 256>>>(ast_edge, cfg_edge);

    k_pull1<<<(2 * NMAX * 16 + 255) / 256, 256>>>(ast_b1, cfg_b1);
    k_pull2<<<(2 * NMAX * 16 + 255) / 256, 256>>>(ast_batch, cfg_batch);

    k_epilogue<<<NG / 8, 128>>>(sem, ast_W2, ast_b2, cfg_W2, cfg_b2,
                                Wg1, bg1, Wsem, bsem, Wg2, bg2,
                                ln_g, ln_b, Wc, bc, out);
}

// round 7
// speedup vs baseline: 2.0237x; 1.1204x over previous
#include <cuda_runtime.h>
#include <cuda_fp16.h>
#include <math.h>

#define NG 1024
#define SEM 768
#define NMAX 100000
#define EMAX 1250000
#define SCAN_B 512
#define SCAN_NB 196   // ceil(100000/512)
#define ZBLK 391      // ceil(NMAX/256)

// ---------------- device scratch (static, allocation-free) ----------------
__device__ int    g_deg   [2][NMAX];
__device__ int    g_rowptr[2][NMAX];
__device__ int    g_cursor[2][NMAX];
__device__ int    g_bsum  [2][SCAN_NB];
__device__ int    g_csr   [2][EMAX];
__device__ int2   g_nd    [2][NMAX];      // {type, dinv bits}
__device__ uint4  g_x     [2][NMAX * 8];  // xd in fp16: 64 halves = 8 x uint4 /node
__device__ float4 g_pool  [2][NG * 16];
__device__ float  g_tab   [2][200 * 64];  // emb @ W1 lookup table

__device__ __forceinline__ void red_add_v4(float* addr, float4 v) {
    asm volatile("red.global.add.v4.f32 [%0], {%1, %2, %3, %4};"
                 :: "l"(addr), "f"(v.x), "f"(v.y), "f"(v.z), "f"(v.w)
                 : "memory");
}
__device__ __forceinline__ float4 ldg4(const float* p) {
    return __ldg((const float4*)p);
}
__device__ __forceinline__ void acc8(float* f, uint4 q) {
    __half2* h = reinterpret_cast<__half2*>(&q);
#pragma unroll
    for (int i = 0; i < 4; i++) {
        float2 p = __half22float2(h[i]);
        f[2 * i] += p.x; f[2 * i + 1] += p.y;
    }
}

// ---------------- kernels ----------------

// init: blocks [0,ZBLK) zero deg/pool; blocks [ZBLK, ZBLK+75) build tab (4 rows each)
__global__ void k_init(const float* __restrict__ embA, const float* __restrict__ W1A,
                       const float* __restrict__ embC, const float* __restrict__ W1C) {
    int b = blockIdx.x;
    if (b < ZBLK) {
        int i = b * 256 + threadIdx.x;
        if (i < NMAX) { g_deg[0][i] = 0; g_deg[1][i] = 0; }
        if (i < NG * 16) {
            g_pool[0][i] = make_float4(0.f, 0.f, 0.f, 0.f);
            g_pool[1][i] = make_float4(0.f, 0.f, 0.f, 0.f);
        }
    } else {
        __shared__ float sx[4][64];
        int sub = threadIdx.x >> 6, j = threadIdx.x & 63;
        int row = (b - ZBLK) * 4 + sub;   // 0..299 exactly
        const float* emb; const float* W; float* tab; int rr;
        if (row < 200) { emb = embA; W = W1A; tab = g_tab[0]; rr = row; }
        else           { emb = embC; W = W1C; tab = g_tab[1]; rr = row - 200; }
        sx[sub][j] = emb[rr * 64 + j];
        __syncthreads();
        float acc = 0.f;
#pragma unroll
        for (int k = 0; k < 64; k++) acc = fmaf(sx[sub][k], W[k * 64 + j], acc);
        tab[rr * 64 + j] = acc;
    }
}

// in-degree counts over dst, both graphs in one launch
__global__ void k_deg(const int* __restrict__ eA, const int* __restrict__ eC) {
    int t = blockIdx.x * blockDim.x + threadIdx.x;
    if (t >= 2 * EMAX) return;
    int s = t >= EMAX; int e = t - s * EMAX;
    const int* edge = s ? eC : eA;
    atomicAdd(&g_deg[s][__ldg(edge + EMAX + e)], 1);
}

// scan pass 1: per-block exclusive scan of deg -> rowptr (local), block totals
__global__ void k_scan1() {
    int s = blockIdx.x / SCAN_NB;
    int blk = blockIdx.x % SCAN_NB;
    int i = blk * SCAN_B + threadIdx.x;
    int val = (i < NMAX) ? g_deg[s][i] : 0;
    __shared__ int sm[SCAN_B];
    sm[threadIdx.x] = val;
    __syncthreads();
#pragma unroll
    for (int off = 1; off < SCAN_B; off <<= 1) {
        int t = (threadIdx.x >= off) ? sm[threadIdx.x - off] : 0;
        __syncthreads();
        sm[threadIdx.x] += t;
        __syncthreads();
    }
    if (i < NMAX) g_rowptr[s][i] = sm[threadIdx.x] - val;
    if (threadIdx.x == SCAN_B - 1) g_bsum[s][blk] = sm[threadIdx.x];
}

// scan pass 2+3 fused: every block redundantly scans the 196 block sums (both s),
// finalizes rowptr/cursor, and inits nd = {type, dinv}
__global__ void k_scan23(const int* __restrict__ tyA, const int* __restrict__ tyC) {
    __shared__ int sb[2][256];
    int tx = threadIdx.x;
    sb[0][tx] = (tx < SCAN_NB) ? g_bsum[0][tx] : 0;
    sb[1][tx] = (tx < SCAN_NB) ? g_bsum[1][tx] : 0;
    __syncthreads();
#pragma unroll
    for (int off = 1; off < 256; off <<= 1) {
        int t0 = (tx >= off) ? sb[0][tx - off] : 0;
        int t1 = (tx >= off) ? sb[1][tx - off] : 0;
        __syncthreads();
        sb[0][tx] += t0; sb[1][tx] += t1;
        __syncthreads();
    }
    int t = blockIdx.x * 256 + tx;
    if (t >= 2 * NMAX) return;
    int s = t >= NMAX; int i = t - s * NMAX;
    int blk2 = i / SCAN_B;
    int boff = (blk2 > 0) ? sb[s][blk2 - 1] : 0;
    int r = g_rowptr[s][i] + boff;
    g_rowptr[s][i] = r;
    g_cursor[s][i] = r;
    float dv = rsqrtf((float)g_deg[s][i] + 1.0f);
    int ty = __ldg((s ? tyC : tyA) + i);
    g_nd[s][i] = make_int2(ty, __float_as_int(dv));
}

// CSR fill: csr[slot of dst] = src
__global__ void k_fill(const int* __restrict__ eA, const int* __restrict__ eC) {
    int t = blockIdx.x * blockDim.x + threadIdx.x;
    if (t >= 2 * EMAX) return;
    int s = t >= EMAX; int e = t - s * EMAX;
    const int* edge = s ? eC : eA;
    int u = __ldg(edge + e);
    int v = __ldg(edge + EMAX + e);
    int slot = atomicAdd(&g_cursor[s][v], 1);
    g_csr[s][slot] = u;
}

// pull layer 1 (table-based), fp32 compute, fp16 store:
// xd_v = dinv_v * relu( dinv_v*(sum_u tab[ty_u]*dinv_u + tab[ty_v]*dinv_v) + b1 )
__global__ void __launch_bounds__(256) k_pull1(const float* __restrict__ b1A,
                                               const float* __restrict__ b1C) {
    int t = blockIdx.x * blockDim.x + threadIdx.x;
    int grp = t >> 4, lane = t & 15;
    int s = grp >= NMAX; int v = grp - s * NMAX;   // grid exact: 2*NMAX*16 threads
    const float4* __restrict__ tab4 = (const float4*)g_tab[s];
    const int2* __restrict__ nd = g_nd[s];

    int2 ndv = __ldg(&nd[v]);
    float dv = __int_as_float(ndv.y);
    float4 tv = tab4[ndv.x * 16 + lane];
    float4 acc = make_float4(tv.x * dv, tv.y * dv, tv.z * dv, tv.w * dv);

    int r = g_rowptr[s][v], d = g_deg[s][v];
    const int* __restrict__ cs = g_csr[s] + r;
    int k = 0;
    for (; k + 4 <= d; k += 4) {
        int i0 = __ldg(cs + k), i1 = __ldg(cs + k + 1);
        int i2 = __ldg(cs + k + 2), i3 = __ldg(cs + k + 3);
        int2 n0 = __ldg(&nd[i0]), n1 = __ldg(&nd[i1]);
        int2 n2 = __ldg(&nd[i2]), n3 = __ldg(&nd[i3]);
        float d0 = __int_as_float(n0.y), d1 = __int_as_float(n1.y);
        float d2 = __int_as_float(n2.y), d3 = __int_as_float(n3.y);
        float4 t0 = tab4[n0.x * 16 + lane];
        float4 t1 = tab4[n1.x * 16 + lane];
        float4 t2 = tab4[n2.x * 16 + lane];
        float4 t3 = tab4[n3.x * 16 + lane];
        acc.x = fmaf(t0.x, d0, acc.x); acc.y = fmaf(t0.y, d0, acc.y);
        acc.z = fmaf(t0.z, d0, acc.z); acc.w = fmaf(t0.w, d0, acc.w);
        acc.x = fmaf(t1.x, d1, acc.x); acc.y = fmaf(t1.y, d1, acc.y);
        acc.z = fmaf(t1.z, d1, acc.z); acc.w = fmaf(t1.w, d1, acc.w);
        acc.x = fmaf(t2.x, d2, acc.x); acc.y = fmaf(t2.y, d2, acc.y);
        acc.z = fmaf(t2.z, d2, acc.z); acc.w = fmaf(t2.w, d2, acc.w);
        acc.x = fmaf(t3.x, d3, acc.x); acc.y = fmaf(t3.y, d3, acc.y);
        acc.z = fmaf(t3.z, d3, acc.z); acc.w = fmaf(t3.w, d3, acc.w);
    }
    for (; k < d; k++) {
        int i0 = __ldg(cs + k);
        int2 n0 = __ldg(&nd[i0]);
        float d0 = __int_as_float(n0.y);
        float4 t0 = tab4[n0.x * 16 + lane];
        acc.x = fmaf(t0.x, d0, acc.x); acc.y = fmaf(t0.y, d0, acc.y);
        acc.z = fmaf(t0.z, d0, acc.z); acc.w = fmaf(t0.w, d0, acc.w);
    }
    float4 bv = ldg4((s ? b1C : b1A) + lane * 4);
    float x0 = dv * fmaxf(fmaf(dv, acc.x, bv.x), 0.f);
    float x1 = dv * fmaxf(fmaf(dv, acc.y, bv.y), 0.f);
    float x2 = dv * fmaxf(fmaf(dv, acc.z, bv.z), 0.f);
    float x3 = dv * fmaxf(fmaf(dv, acc.w, bv.w), 0.f);
    __half2 h0 = __floats2half2_rn(x0, x1);
    __half2 h1 = __floats2half2_rn(x2, x3);
    uint2 u;
    u.x = *reinterpret_cast<unsigned int*>(&h0);
    u.y = *reinterpret_cast<unsigned int*>(&h1);
    ((uint2*)g_x[s])[v * 16 + lane] = u;
}

// pull layer 2 + segmented pooling. 8 lanes/node, 32 nodes/block (grid exact).
// val_v = dinv_v * (sum_u xd_u + xd_v); pool[batch_v] += val_v via smem segments.
__global__ void __launch_bounds__(256) k_pull2(const int* __restrict__ batchA,
                                               const int* __restrict__ batchC) {
    int blk = blockIdx.x;              // 6250 blocks: 3125 per graph
    int s = blk >= 3125;
    int v0 = (blk - s * 3125) * 32;
    int li = threadIdx.x >> 3;         // local node 0..31
    int l  = threadIdx.x & 7;          // feature chunk 0..7 (8 floats each)
    int v = v0 + li;

    const uint4* __restrict__ xd4 = (const uint4*)g_x[s];
    float f[8] = {0.f, 0.f, 0.f, 0.f, 0.f, 0.f, 0.f, 0.f};

    acc8(f, __ldg(&xd4[v * 8 + l]));   // self term
    int r = g_rowptr[s][v], d = g_deg[s][v];
    const int* __restrict__ cs = g_csr[s] + r;
    int k = 0;
    for (; k + 4 <= d; k += 4) {
        int i0 = __ldg(cs + k), i1 = __ldg(cs + k + 1);
        int i2 = __ldg(cs + k + 2), i3 = __ldg(cs + k + 3);
        uint4 q0 = __ldg(&xd4[i0 * 8 + l]);
        uint4 q1 = __ldg(&xd4[i1 * 8 + l]);
        uint4 q2 = __ldg(&xd4[i2 * 8 + l]);
        uint4 q3 = __ldg(&xd4[i3 * 8 + l]);
        acc8(f, q0); acc8(f, q1); acc8(f, q2); acc8(f, q3);
    }
    for (; k < d; k++) {
        int i0 = __ldg(cs + k);
        acc8(f, __ldg(&xd4[i0 * 8 + l]));
    }
    float dv = __int_as_float(__ldg(&g_nd[s][v]).y);

    __shared__ float sp[32][68];   // padded to break bank conflicts
    __shared__ int   sb[32];
#pragma unroll
    for (int i = 0; i < 8; i++) sp[li][l * 8 + i] = f[i] * dv;
    if (threadIdx.x < 32)
        sb[threadIdx.x] = __ldg((s ? batchC : batchA) + v0 + threadIdx.x);
    __syncthreads();

    int gId = sb[li];
    bool head = (li == 0) || (sb[li - 1] != gId);
    if (head) {
        int len = 1;
        while (li + len < 32 && sb[li + len] == gId) len++;
        float t0 = 0, t1 = 0, t2 = 0, t3 = 0, t4 = 0, t5 = 0, t6 = 0, t7 = 0;
        for (int j = li; j < li + len; j++) {
            t0 += sp[j][l * 8 + 0]; t1 += sp[j][l * 8 + 1];
            t2 += sp[j][l * 8 + 2]; t3 += sp[j][l * 8 + 3];
            t4 += sp[j][l * 8 + 4]; t5 += sp[j][l * 8 + 5];
            t6 += sp[j][l * 8 + 6]; t7 += sp[j][l * 8 + 7];
        }
        float* dst = (float*)&g_pool[s][gId * 16];
        red_add_v4(dst + l * 8,     make_float4(t0, t1, t2, t3));
        red_add_v4(dst + l * 8 + 4, make_float4(t4, t5, t6, t7));
    }
}

// count of nodes with batch==g in sorted array (two binary searches)
__device__ __forceinline__ int cnt_graph(const int* __restrict__ b, int g) {
    int lo = 0, hi = NMAX;
    while (lo < hi) { int m = (lo + hi) >> 1; if (__ldg(b + m) < g) lo = m + 1; else hi = m; }
    int lb = lo;
    lo = 0; hi = NMAX;
    while (lo < hi) { int m = (lo + hi) >> 1; if (__ldg(b + m) <= g) lo = m + 1; else hi = m; }
    return lo - lb;
}

// epilogue: 128 blocks x 128 thr; 8 graphs/block; 16 lanes x 4 cols per graph.
__global__ void __launch_bounds__(128) k_epilogue(
    const float* __restrict__ sem,
    const int* __restrict__ batchA, const int* __restrict__ batchC,
    const float* __restrict__ W2A, const float* __restrict__ b2A,
    const float* __restrict__ W2C, const float* __restrict__ b2C,
    const float* __restrict__ Wg1, const float* __restrict__ bg1,
    const float* __restrict__ Wsem, const float* __restrict__ bsem,
    const float* __restrict__ Wg2, const float* __restrict__ bg2,
    const float* __restrict__ ln_g, const float* __restrict__ ln_b,
    const float* __restrict__ Wc, const float* __restrict__ bc,
    float* __restrict__ out) {
    int sg = threadIdx.x >> 4;     // subgroup 0..7 (one graph each)
    int l  = threadIdx.x & 15;
    int g  = blockIdx.x * 8 + sg;
    int j0 = l * 4;

    __shared__ float sPA[8][64], sPC[8][64];
    __shared__ float sA [8][64], sB [8][64];
    __shared__ float sHS[8][64], sHM[8][64];

    float4 PA = g_pool[0][g * 16 + l];
    float4 PC = g_pool[1][g * 16 + l];
    *(float4*)&sPA[sg][j0] = PA;
    *(float4*)&sPC[sg][j0] = PC;
    float cntA = (float)cnt_graph(batchA, g);
    float cntC = (float)cnt_graph(batchC, g);
    __syncwarp();

    float4 a = make_float4(0.f, 0.f, 0.f, 0.f);
    float4 b = make_float4(0.f, 0.f, 0.f, 0.f);
#pragma unroll 4
    for (int k = 0; k < 64; k++) {
        float pa = sPA[sg][k], pc = sPC[sg][k];
        float4 wa = ldg4(W2A + k * 64 + j0);
        float4 wc = ldg4(W2C + k * 64 + j0);
        a.x = fmaf(pa, wa.x, a.x); a.y = fmaf(pa, wa.y, a.y);
        a.z = fmaf(pa, wa.z, a.z); a.w = fmaf(pa, wa.w, a.w);
        b.x = fmaf(pc, wc.x, b.x); b.y = fmaf(pc, wc.y, b.y);
        b.z = fmaf(pc, wc.z, b.z); b.w = fmaf(pc, wc.w, b.w);
    }
    {
        float4 ba = ldg4(b2A + j0), bb = ldg4(b2C + j0);
        a.x = fmaf(cntA, ba.x, a.x); a.y = fmaf(cntA, ba.y, a.y);
        a.z = fmaf(cntA, ba.z, a.z); a.w = fmaf(cntA, ba.w, a.w);
        b.x = fmaf(cntC, bb.x, b.x); b.y = fmaf(cntC, bb.y, b.y);
        b.z = fmaf(cntC, bb.z, b.z); b.w = fmaf(cntC, bb.w, b.w);
    }
    *(float4*)&sA[sg][j0] = a;
    *(float4*)&sB[sg][j0] = b;
    __syncwarp();

    // gate 1
    float4 acc = ldg4(bg1 + j0);
#pragma unroll 4
    for (int k = 0; k < 64; k++) {
        float va = sA[sg][k];
        float4 w = ldg4(Wg1 + k * 64 + j0);
        acc.x = fmaf(va, w.x, acc.x); acc.y = fmaf(va, w.y, acc.y);
        acc.z = fmaf(va, w.z, acc.z); acc.w = fmaf(va, w.w, acc.w);
    }
#pragma unroll 4
    for (int k = 0; k < 64; k++) {
        float vb = sB[sg][k];
        float4 w = ldg4(Wg1 + (64 + k) * 64 + j0);
        acc.x = fmaf(vb, w.x, acc.x); acc.y = fmaf(vb, w.y, acc.y);
        acc.z = fmaf(vb, w.z, acc.z); acc.w = fmaf(vb, w.w, acc.w);
    }
    float4 g1;
    g1.x = 1.f / (1.f + expf(-acc.x));
    g1.y = 1.f / (1.f + expf(-acc.y));
    g1.z = 1.f / (1.f + expf(-acc.z));
    g1.w = 1.f / (1.f + expf(-acc.w));
    float4 hst;
    hst.x = g1.x * a.x + (1.f - g1.x) * b.x;
    hst.y = g1.y * a.y + (1.f - g1.y) * b.y;
    hst.z = g1.z * a.z + (1.f - g1.z) * b.z;
    hst.w = g1.w * a.w + (1.f - g1.w) * b.w;

    // sem projection
    float4 ac2 = ldg4(bsem + j0);
    const float* semrow = sem + g * SEM;
#pragma unroll 4
    for (int k = 0; k < SEM; k += 4) {
        float4 s4 = ldg4(semrow + k);
        float4 w0 = ldg4(Wsem + (k + 0) * 64 + j0);
        float4 w1 = ldg4(Wsem + (k + 1) * 64 + j0);
        float4 w2 = ldg4(Wsem + (k + 2) * 64 + j0);
        float4 w3 = ldg4(Wsem + (k + 3) * 64 + j0);
        ac2.x = fmaf(s4.x, w0.x, ac2.x); ac2.y = fmaf(s4.x, w0.y, ac2.y);
        ac2.z = fmaf(s4.x, w0.z, ac2.z); ac2.w = fmaf(s4.x, w0.w, ac2.w);
        ac2.x = fmaf(s4.y, w1.x, ac2.x); ac2.y = fmaf(s4.y, w1.y, ac2.y);
        ac2.z = fmaf(s4.y, w1.z, ac2.z); ac2.w = fmaf(s4.y, w1.w, ac2.w);
        ac2.x = fmaf(s4.z, w2.x, ac2.x); ac2.y = fmaf(s4.z, w2.y, ac2.y);
        ac2.z = fmaf(s4.z, w2.z, ac2.z); ac2.w = fmaf(s4.z, w2.w, ac2.w);
        ac2.x = fmaf(s4.w, w3.x, ac2.x); ac2.y = fmaf(s4.w, w3.y, ac2.y);
        ac2.z = fmaf(s4.w, w3.z, ac2.z); ac2.w = fmaf(s4.w, w3.w, ac2.w);
    }
    float4 hm;
    hm.x = fmaxf(ac2.x, 0.f); hm.y = fmaxf(ac2.y, 0.f);
    hm.z = fmaxf(ac2.z, 0.f); hm.w = fmaxf(ac2.w, 0.f);

    *(float4*)&sHS[sg][j0] = hst;
    *(float4*)&sHM[sg][j0] = hm;
    __syncwarp();

    // gate 2
    float4 ac3 = ldg4(bg2 + j0);
#pragma unroll 4
    for (int k = 0; k < 64; k++) {
        float vh = sHS[sg][k];
        float4 w = ldg4(Wg2 + k * 64 + j0);
        ac3.x = fmaf(vh, w.x, ac3.x); ac3.y = fmaf(vh, w.y, ac3.y);
        ac3.z = fmaf(vh, w.z, ac3.z); ac3.w = fmaf(vh, w.w, ac3.w);
    }
#pragma unroll 4
    for (int k = 0; k < 64; k++) {
        float vm = sHM[sg][k];
        float4 w = ldg4(Wg2 + (64 + k) * 64 + j0);
        ac3.x = fmaf(vm, w.x, ac3.x); ac3.y = fmaf(vm, w.y, ac3.y);
        ac3.z = fmaf(vm, w.z, ac3.z); ac3.w = fmaf(vm, w.w, ac3.w);
    }
    float4 g2;
    g2.x = 1.f / (1.f + expf(-ac3.x));
    g2.y = 1.f / (1.f + expf(-ac3.y));
    g2.z = 1.f / (1.f + expf(-ac3.z));
    g2.w = 1.f / (1.f + expf(-ac3.w));
    float4 h;
    h.x = g2.x * hst.x + (1.f - g2.x) * hm.x;
    h.y = g2.y * hst.y + (1.f - g2.y) * hm.y;
    h.z = g2.z * hst.z + (1.f - g2.z) * hm.z;
    h.w = g2.w * hst.w + (1.f - g2.w) * hm.w;

    // layernorm over 64 (16-lane shfl reduce)
    float s1 = (h.x + h.y) + (h.z + h.w);
    float s2 = (h.x * h.x + h.y * h.y) + (h.z * h.z + h.w * h.w);
#pragma unroll
    for (int m = 1; m < 16; m <<= 1) {
        s1 += __shfl_xor_sync(0xFFFFFFFFu, s1, m);
        s2 += __shfl_xor_sync(0xFFFFFFFFu, s2, m);
    }
    float mu  = s1 * (1.f / 64.f);
    float var = s2 * (1.f / 64.f) - mu * mu;
    float rstd = rsqrtf(var + 1e-5f);
    float4 lg = ldg4(ln_g + j0), lb = ldg4(ln_b + j0);
    float4 hn;
    hn.x = (h.x - mu) * rstd * lg.x + lb.x;
    hn.y = (h.y - mu) * rstd * lg.y + lb.y;
    hn.z = (h.z - mu) * rstd * lg.z + lb.z;
    hn.w = (h.w - mu) * rstd * lg.w + lb.w;

    // classifier (NCLS=2): Wc is [64,2]
    float4 wc0 = ldg4(Wc + j0 * 2);
    float4 wc1 = ldg4(Wc + j0 * 2 + 4);
    float o0 = hn.x * wc0.x + hn.y * wc0.z + hn.z * wc1.x + hn.w * wc1.z;
    float o1 = hn.x * wc0.y + hn.y * wc0.w + hn.z * wc1.y + hn.w * wc1.w;
#pragma unroll
    for (int m = 1; m < 16; m <<= 1) {
        o0 += __shfl_xor_sync(0xFFFFFFFFu, o0, m);
        o1 += __shfl_xor_sync(0xFFFFFFFFu, o1, m);
    }
    if (l == 0) {
        out[g * 2 + 0] = o0 + __ldg(bc + 0);
        out[g * 2 + 1] = o1 + __ldg(bc + 1);
    }
}

// ---------------- launch ----------------
extern "C" void kernel_launch(void* const* d_in, const int* in_sizes, int n_in,
                              void* d_out, int out_size) {
    const int*   ast_type  = (const int*)  d_in[0];
    const int*   ast_edge  = (const int*)  d_in[1];
    const int*   ast_batch = (const int*)  d_in[2];
    const int*   cfg_type  = (const int*)  d_in[3];
    const int*   cfg_edge  = (const int*)  d_in[4];
    const int*   cfg_batch = (const int*)  d_in[5];
    const float* sem       = (const float*)d_in[6];
    const float* ast_emb   = (const float*)d_in[7];
    const float* cfg_emb   = (const float*)d_in[8];
    const float* ast_W1    = (const float*)d_in[9];
    const float* ast_b1    = (const float*)d_in[10];
    const float* ast_W2    = (const float*)d_in[11];
    const float* ast_b2    = (const float*)d_in[12];
    const float* cfg_W1    = (const float*)d_in[13];
    const float* cfg_b1    = (const float*)d_in[14];
    const float* cfg_W2    = (const float*)d_in[15];
    const float* cfg_b2    = (const float*)d_in[16];
    const float* Wg1       = (const float*)d_in[17];
    const float* bg1       = (const float*)d_in[18];
    const float* Wsem      = (const float*)d_in[19];
    const float* bsem      = (const float*)d_in[20];
    const float* Wg2       = (const float*)d_in[21];
    const float* bg2       = (const float*)d_in[22];
    const float* ln_g      = (const float*)d_in[23];
    const float* ln_b      = (const float*)d_in[24];
    const float* Wc        = (const float*)d_in[25];
    const float* bc        = (const float*)d_in[26];
    float* out = (float*)d_out;

    k_init<<<ZBLK + 75, 256>>>(ast_emb, ast_W1, cfg_emb, cfg_W1);
    k_deg<<<(2 * EMAX + 255) / 256, 256>>>(ast_edge, cfg_edge);
    k_scan1<<<2 * SCAN_NB, SCAN_B>>>();
    k_scan23<<<(2 * NMAX + 255) / 256, 256>>>(ast_type, cfg_type);
    k_fill<<<(2 * EMAX + 255) / 256, 256>>>(ast_edge, cfg_edge);

    k_pull1<<<2 * NMAX * 16 / 256, 256>>>(ast_b1, cfg_b1);
    k_pull2<<<2 * NMAX / 32, 256>>>(ast_batch, cfg_batch);

    k_epilogue<<<NG / 8, 128>>>(sem, ast_batch, cfg_batch,
                                ast_W2, ast_b2, cfg_W2, cfg_b2,
                                Wg1, bg1, Wsem, bsem, Wg2, bg2,
                                ln_g, ln_b, Wc, bc, out);
}

// round 8
// speedup vs baseline: 2.0830x; 1.0293x over previous
#include <cuda_runtime.h>
#include <cuda_fp16.h>
#include <math.h>

#define NG 1024
#define SEM 768
#define NMAX 100000
#define EMAX 1250000
#define SCAN_B 512
#define SCAN_NB 196   // ceil(100000/512)
#define ZBLK 391      // ceil(NMAX/256)

// ---------------- device scratch (static, allocation-free) ----------------
__device__ int    g_deg   [2][NMAX];
__device__ int    g_rowptr[2][NMAX];
__device__ int    g_cursor[2][NMAX];
__device__ int    g_bsum  [2][SCAN_NB];
__device__ int    g_csr   [2][EMAX];
__device__ int2   g_nd    [2][NMAX];      // {type, dinv bits}
__device__ uint4  g_x     [2][NMAX * 8];  // xd in fp16: 64 halves = 8 x uint4 /node
__device__ float4 g_pool  [2][NG * 16];
__device__ float  g_tab   [2][200 * 64];  // emb @ W1 lookup table

__device__ __forceinline__ void red_add_v4(float* addr, float4 v) {
    asm volatile("red.global.add.v4.f32 [%0], {%1, %2, %3, %4};"
                 :: "l"(addr), "f"(v.x), "f"(v.y), "f"(v.z), "f"(v.w)
                 : "memory");
}
__device__ __forceinline__ float4 ldg4(const float* p) {
    return __ldg((const float4*)p);
}
__device__ __forceinline__ void acc8(float* f, uint4 q) {
    __half2* h = reinterpret_cast<__half2*>(&q);
#pragma unroll
    for (int i = 0; i < 4; i++) {
        float2 p = __half22float2(h[i]);
        f[2 * i] += p.x; f[2 * i + 1] += p.y;
    }
}

// ---------------- kernels ----------------

// init: blocks [0,ZBLK) zero deg/pool; blocks [ZBLK, ZBLK+75) build tab (4 rows each)
__global__ void k_init(const float* __restrict__ embA, const float* __restrict__ W1A,
                       const float* __restrict__ embC, const float* __restrict__ W1C) {
    int b = blockIdx.x;
    if (b < ZBLK) {
        int i = b * 256 + threadIdx.x;
        if (i < NMAX) { g_deg[0][i] = 0; g_deg[1][i] = 0; }
        if (i < NG * 16) {
            g_pool[0][i] = make_float4(0.f, 0.f, 0.f, 0.f);
            g_pool[1][i] = make_float4(0.f, 0.f, 0.f, 0.f);
        }
    } else {
        __shared__ float sx[4][64];
        int sub = threadIdx.x >> 6, j = threadIdx.x & 63;
        int row = (b - ZBLK) * 4 + sub;   // 0..299 exactly
        const float* emb; const float* W; float* tab; int rr;
        if (row < 200) { emb = embA; W = W1A; tab = g_tab[0]; rr = row; }
        else           { emb = embC; W = W1C; tab = g_tab[1]; rr = row - 200; }
        sx[sub][j] = emb[rr * 64 + j];
        __syncthreads();
        float acc = 0.f;
#pragma unroll
        for (int k = 0; k < 64; k++) acc = fmaf(sx[sub][k], W[k * 64 + j], acc);
        tab[rr * 64 + j] = acc;
    }
}

// in-degree counts over dst, int4 = 4 edges per thread
__global__ void k_deg(const int* __restrict__ eA, const int* __restrict__ eC) {
    int t = blockIdx.x * blockDim.x + threadIdx.x;
    const int Q = EMAX / 4;            // 312500
    if (t >= 2 * Q) return;
    int s = t >= Q; int e = t - s * Q;
    const int4* dst4 = (const int4*)((s ? eC : eA) + EMAX);
    int4 q = __ldg(&dst4[e]);
    atomicAdd(&g_deg[s][q.x], 1);
    atomicAdd(&g_deg[s][q.y], 1);
    atomicAdd(&g_deg[s][q.z], 1);
    atomicAdd(&g_deg[s][q.w], 1);
}

// scan pass 1: per-block exclusive scan of deg -> rowptr (local), block totals
__global__ void k_scan1() {
    int s = blockIdx.x / SCAN_NB;
    int blk = blockIdx.x % SCAN_NB;
    int i = blk * SCAN_B + threadIdx.x;
    int val = (i < NMAX) ? g_deg[s][i] : 0;
    __shared__ int sm[SCAN_B];
    sm[threadIdx.x] = val;
    __syncthreads();
#pragma unroll
    for (int off = 1; off < SCAN_B; off <<= 1) {
        int t = (threadIdx.x >= off) ? sm[threadIdx.x - off] : 0;
        __syncthreads();
        sm[threadIdx.x] += t;
        __syncthreads();
    }
    if (i < NMAX) g_rowptr[s][i] = sm[threadIdx.x] - val;
    if (threadIdx.x == SCAN_B - 1) g_bsum[s][blk] = sm[threadIdx.x];
}

// scan pass 2+3 fused: every block redundantly scans the 196 block sums (both s),
// finalizes rowptr/cursor, and inits nd = {type, dinv}
__global__ void k_scan23(const int* __restrict__ tyA, const int* __restrict__ tyC) {
    __shared__ int sb[2][256];
    int tx = threadIdx.x;
    sb[0][tx] = (tx < SCAN_NB) ? g_bsum[0][tx] : 0;
    sb[1][tx] = (tx < SCAN_NB) ? g_bsum[1][tx] : 0;
    __syncthreads();
#pragma unroll
    for (int off = 1; off < 256; off <<= 1) {
        int t0 = (tx >= off) ? sb[0][tx - off] : 0;
        int t1 = (tx >= off) ? sb[1][tx - off] : 0;
        __syncthreads();
        sb[0][tx] += t0; sb[1][tx] += t1;
        __syncthreads();
    }
    int t = blockIdx.x * 256 + tx;
    if (t >= 2 * NMAX) return;
    int s = t >= NMAX; int i = t - s * NMAX;
    int blk2 = i / SCAN_B;
    int boff = (blk2 > 0) ? sb[s][blk2 - 1] : 0;
    int r = g_rowptr[s][i] + boff;
    g_rowptr[s][i] = r;
    g_cursor[s][i] = r;
    float dv = rsqrtf((float)g_deg[s][i] + 1.0f);
    int ty = __ldg((s ? tyC : tyA) + i);
    g_nd[s][i] = make_int2(ty, __float_as_int(dv));
}

// CSR fill, int4 = 4 edges per thread
__global__ void k_fill(const int* __restrict__ eA, const int* __restrict__ eC) {
    int t = blockIdx.x * blockDim.x + threadIdx.x;
    const int Q = EMAX / 4;
    if (t >= 2 * Q) return;
    int s = t >= Q; int e = t - s * Q;
    const int* edge = s ? eC : eA;
    int4 us = __ldg((const int4*)edge + e);
    int4 vs = __ldg((const int4*)(edge + EMAX) + e);
    int* cur = g_cursor[s];
    int* csr = g_csr[s];
    csr[atomicAdd(&cur[vs.x], 1)] = us.x;
    csr[atomicAdd(&cur[vs.y], 1)] = us.y;
    csr[atomicAdd(&cur[vs.z], 1)] = us.z;
    csr[atomicAdd(&cur[vs.w], 1)] = us.w;
}

// pull layer 1, 8 lanes/node, 32 nodes/block (grid exact):
// xd_v = dinv_v * relu( dinv_v*(sum_u tab[ty_u]*dinv_u + tab[ty_v]*dinv_v) + b1 )
__global__ void __launch_bounds__(256) k_pull1(const float* __restrict__ b1A,
                                               const float* __restrict__ b1C) {
    int blk = blockIdx.x;              // 6250 blocks: 3125 per graph
    int s = blk >= 3125;
    int v = (blk - s * 3125) * 32 + (threadIdx.x >> 3);
    int l = threadIdx.x & 7;           // feature chunk: floats [8l, 8l+8)
    const float4* __restrict__ tab4 = (const float4*)g_tab[s];
    const int2* __restrict__ nd = g_nd[s];

    int2 ndv = __ldg(&nd[v]);
    float dv = __int_as_float(ndv.y);
    float a[8];
    {
        float4 t0 = tab4[ndv.x * 16 + l * 2];
        float4 t1 = tab4[ndv.x * 16 + l * 2 + 1];
        a[0] = t0.x * dv; a[1] = t0.y * dv; a[2] = t0.z * dv; a[3] = t0.w * dv;
        a[4] = t1.x * dv; a[5] = t1.y * dv; a[6] = t1.z * dv; a[7] = t1.w * dv;
    }

    int r = g_rowptr[s][v], d = g_deg[s][v];
    const int* __restrict__ cs = g_csr[s] + r;

#define NB1(u) do { \
        int2 n_ = __ldg(&nd[(u)]); \
        float du_ = __int_as_float(n_.y); \
        float4 p0_ = tab4[n_.x * 16 + l * 2]; \
        float4 p1_ = tab4[n_.x * 16 + l * 2 + 1]; \
        a[0] = fmaf(p0_.x, du_, a[0]); a[1] = fmaf(p0_.y, du_, a[1]); \
        a[2] = fmaf(p0_.z, du_, a[2]); a[3] = fmaf(p0_.w, du_, a[3]); \
        a[4] = fmaf(p1_.x, du_, a[4]); a[5] = fmaf(p1_.y, du_, a[5]); \
        a[6] = fmaf(p1_.z, du_, a[6]); a[7] = fmaf(p1_.w, du_, a[7]); \
    } while (0)

    int k = 0;
    int pe = (4 - (r & 3)) & 3; if (pe > d) pe = d;
    for (; k < pe; k++) NB1(__ldg(cs + k));
    for (; k + 4 <= d; k += 4) {
        int4 q = __ldg((const int4*)(cs + k));
        NB1(q.x); NB1(q.y); NB1(q.z); NB1(q.w);
    }
    for (; k < d; k++) NB1(__ldg(cs + k));
#undef NB1

    const float* b1 = s ? b1C : b1A;
    float4 b0 = ldg4(b1 + l * 8), b1v = ldg4(b1 + l * 8 + 4);
    float x0 = dv * fmaxf(fmaf(dv, a[0], b0.x), 0.f);
    float x1 = dv * fmaxf(fmaf(dv, a[1], b0.y), 0.f);
    float x2 = dv * fmaxf(fmaf(dv, a[2], b0.z), 0.f);
    float x3 = dv * fmaxf(fmaf(dv, a[3], b0.w), 0.f);
    float x4 = dv * fmaxf(fmaf(dv, a[4], b1v.x), 0.f);
    float x5 = dv * fmaxf(fmaf(dv, a[5], b1v.y), 0.f);
    float x6 = dv * fmaxf(fmaf(dv, a[6], b1v.z), 0.f);
    float x7 = dv * fmaxf(fmaf(dv, a[7], b1v.w), 0.f);
    __half2 h0 = __floats2half2_rn(x0, x1);
    __half2 h1 = __floats2half2_rn(x2, x3);
    __half2 h2 = __floats2half2_rn(x4, x5);
    __half2 h3 = __floats2half2_rn(x6, x7);
    uint4 u;
    u.x = *reinterpret_cast<unsigned int*>(&h0);
    u.y = *reinterpret_cast<unsigned int*>(&h1);
    u.z = *reinterpret_cast<unsigned int*>(&h2);
    u.w = *reinterpret_cast<unsigned int*>(&h3);
    g_x[s][v * 8 + l] = u;
}

// pull layer 2 + segmented pooling. 8 lanes/node, 32 nodes/block (grid exact).
// val_v = dinv_v * (sum_u xd_u + xd_v); pool[batch_v] += val_v via smem segments.
__global__ void __launch_bounds__(256) k_pull2(const int* __restrict__ batchA,
                                               const int* __restrict__ batchC) {
    int blk = blockIdx.x;              // 6250 blocks: 3125 per graph
    int s = blk >= 3125;
    int v0 = (blk - s * 3125) * 32;
    int li = threadIdx.x >> 3;         // local node 0..31
    int l  = threadIdx.x & 7;          // feature chunk 0..7 (8 floats each)
    int v = v0 + li;

    const uint4* __restrict__ xd4 = (const uint4*)g_x[s];
    float f[8] = {0.f, 0.f, 0.f, 0.f, 0.f, 0.f, 0.f, 0.f};

    acc8(f, __ldg(&xd4[v * 8 + l]));   // self term
    int r = g_rowptr[s][v], d = g_deg[s][v];
    const int* __restrict__ cs = g_csr[s] + r;
    int k = 0;
    int pe = (4 - (r & 3)) & 3; if (pe > d) pe = d;
    for (; k < pe; k++) acc8(f, __ldg(&xd4[__ldg(cs + k) * 8 + l]));
    for (; k + 4 <= d; k += 4) {
        int4 q = __ldg((const int4*)(cs + k));
        uint4 q0 = __ldg(&xd4[q.x * 8 + l]);
        uint4 q1 = __ldg(&xd4[q.y * 8 + l]);
        uint4 q2 = __ldg(&xd4[q.z * 8 + l]);
        uint4 q3 = __ldg(&xd4[q.w * 8 + l]);
        acc8(f, q0); acc8(f, q1); acc8(f, q2); acc8(f, q3);
    }
    for (; k < d; k++) acc8(f, __ldg(&xd4[__ldg(cs + k) * 8 + l]));
    float dv = __int_as_float(__ldg(&g_nd[s][v]).y);

    __shared__ float sp[32][68];   // padded to break bank conflicts
    __shared__ int   sb[32];
#pragma unroll
    for (int i = 0; i < 8; i++) sp[li][l * 8 + i] = f[i] * dv;
    if (threadIdx.x < 32)
        sb[threadIdx.x] = __ldg((s ? batchC : batchA) + v0 + threadIdx.x);
    __syncthreads();

    int gId = sb[li];
    bool head = (li == 0) || (sb[li - 1] != gId);
    if (head) {
        int len = 1;
        while (li + len < 32 && sb[li + len] == gId) len++;
        float t0 = 0, t1 = 0, t2 = 0, t3 = 0, t4 = 0, t5 = 0, t6 = 0, t7 = 0;
        for (int j = li; j < li + len; j++) {
            t0 += sp[j][l * 8 + 0]; t1 += sp[j][l * 8 + 1];
            t2 += sp[j][l * 8 + 2]; t3 += sp[j][l * 8 + 3];
            t4 += sp[j][l * 8 + 4]; t5 += sp[j][l * 8 + 5];
            t6 += sp[j][l * 8 + 6]; t7 += sp[j][l * 8 + 7];
        }
        float* dst = (float*)&g_pool[s][gId * 16];
        red_add_v4(dst + l * 8,     make_float4(t0, t1, t2, t3));
        red_add_v4(dst + l * 8 + 4, make_float4(t4, t5, t6, t7));
    }
}

// count of nodes with batch==g in sorted array (two binary searches)
__device__ __forceinline__ int cnt_graph(const int* __restrict__ b, int g) {
    int lo = 0, hi = NMAX;
    while (lo < hi) { int m = (lo + hi) >> 1; if (__ldg(b + m) < g) lo = m + 1; else hi = m; }
    int lb = lo;
    lo = 0; hi = NMAX;
    while (lo < hi) { int m = (lo + hi) >> 1; if (__ldg(b + m) <= g) lo = m + 1; else hi = m; }
    return lo - lb;
}

// epilogue: 128 blocks x 128 thr; 8 graphs/block; 16 lanes x 4 cols per graph.
__global__ void __launch_bounds__(128) k_epilogue(
    const float* __restrict__ sem,
    const int* __restrict__ batchA, const int* __restrict__ batchC,
    const float* __restrict__ W2A, const float* __restrict__ b2A,
    const float* __restrict__ W2C, const float* __restrict__ b2C,
    const float* __restrict__ Wg1, const float* __restrict__ bg1,
    const float* __restrict__ Wsem, const float* __restrict__ bsem,
    const float* __restrict__ Wg2, const float* __restrict__ bg2,
    const float* __restrict__ ln_g, const float* __restrict__ ln_b,
    const float* __restrict__ Wc, const float* __restrict__ bc,
    float* __restrict__ out) {
    int sg = threadIdx.x >> 4;     // subgroup 0..7 (one graph each)
    int l  = threadIdx.x & 15;
    int g  = blockIdx.x * 8 + sg;
    int j0 = l * 4;

    __shared__ float sPA[8][64], sPC[8][64];
    __shared__ float sA [8][64], sB [8][64];
    __shared__ float sHS[8][64], sHM[8][64];

    float4 PA = g_pool[0][g * 16 + l];
    float4 PC = g_pool[1][g * 16 + l];
    *(float4*)&sPA[sg][j0] = PA;
    *(float4*)&sPC[sg][j0] = PC;
    float cntA = (float)cnt_graph(batchA, g);
    float cntC = (float)cnt_graph(batchC, g);
    __syncwarp();

    float4 a = make_float4(0.f, 0.f, 0.f, 0.f);
    float4 b = make_float4(0.f, 0.f, 0.f, 0.f);
#pragma unroll 4
    for (int k = 0; k < 64; k++) {
        float pa = sPA[sg][k], pc = sPC[sg][k];
        float4 wa = ldg4(W2A + k * 64 + j0);
        float4 wc = ldg4(W2C + k * 64 + j0);
        a.x = fmaf(pa, wa.x, a.x); a.y = fmaf(pa, wa.y, a.y);
        a.z = fmaf(pa, wa.z, a.z); a.w = fmaf(pa, wa.w, a.w);
        b.x = fmaf(pc, wc.x, b.x); b.y = fmaf(pc, wc.y, b.y);
        b.z = fmaf(pc, wc.z, b.z); b.w = fmaf(pc, wc.w, b.w);
    }
    {
        float4 ba = ldg4(b2A + j0), bb = ldg4(b2C + j0);
        a.x = fmaf(cntA, ba.x, a.x); a.y = fmaf(cntA, ba.y, a.y);
        a.z = fmaf(cntA, ba.z, a.z); a.w = fmaf(cntA, ba.w, a.w);
        b.x = fmaf(cntC, bb.x, b.x); b.y = fmaf(cntC, bb.y, b.y);
        b.z = fmaf(cntC, bb.z, b.z); b.w = fmaf(cntC, bb.w, b.w);
    }
    *(float4*)&sA[sg][j0] = a;
    *(float4*)&sB[sg][j0] = b;
    __syncwarp();

    // gate 1
    float4 acc = ldg4(bg1 + j0);
#pragma unroll 4
    for (int k = 0; k < 64; k++) {
        float va = sA[sg][k];
        float4 w = ldg4(Wg1 + k * 64 + j0);
        acc.x = fmaf(va, w.x, acc.x); acc.y = fmaf(va, w.y, acc.y);
        acc.z = fmaf(va, w.z, acc.z); acc.w = fmaf(va, w.w, acc.w);
    }
#pragma unroll 4
    for (int k = 0; k < 64; k++) {
        float vb = sB[sg][k];
        float4 w = ldg4(Wg1 + (64 + k) * 64 + j0);
        acc.x = fmaf(vb, w.x, acc.x); acc.y = fmaf(vb, w.y, acc.y);
        acc.z = fmaf(vb, w.z, acc.z); acc.w = fmaf(vb, w.w, acc.w);
    }
    float4 g1;
    g1.x = 1.f / (1.f + expf(-acc.x));
    g1.y = 1.f / (1.f + expf(-acc.y));
    g1.z = 1.f / (1.f + expf(-acc.z));
    g1.w = 1.f / (1.f + expf(-acc.w));
    float4 hst;
    hst.x = g1.x * a.x + (1.f - g1.x) * b.x;
    hst.y = g1.y * a.y + (1.f - g1.y) * b.y;
    hst.z = g1.z * a.z + (1.f - g1.z) * b.z;
    hst.w = g1.w * a.w + (1.f - g1.w) * b.w;

    // sem projection
    float4 ac2 = ldg4(bsem + j0);
    const float* semrow = sem + g * SEM;
#pragma unroll 4
    for (int k = 0; k < SEM; k += 4) {
        float4 s4 = ldg4(semrow + k);
        float4 w0 = ldg4(Wsem + (k + 0) * 64 + j0);
        float4 w1 = ldg4(Wsem + (k + 1) * 64 + j0);
        float4 w2 = ldg4(Wsem + (k + 2) * 64 + j0);
        float4 w3 = ldg4(Wsem + (k + 3) * 64 + j0);
        ac2.x = fmaf(s4.x, w0.x, ac2.x); ac2.y = fmaf(s4.x, w0.y, ac2.y);
        ac2.z = fmaf(s4.x, w0.z, ac2.z); ac2.w = fmaf(s4.x, w0.w, ac2.w);
        ac2.x = fmaf(s4.y, w1.x, ac2.x); ac2.y = fmaf(s4.y, w1.y, ac2.y);
        ac2.z = fmaf(s4.y, w1.z, ac2.z); ac2.w = fmaf(s4.y, w1.w, ac2.w);
        ac2.x = fmaf(s4.z, w2.x, ac2.x); ac2.y = fmaf(s4.z, w2.y, ac2.y);
        ac2.z = fmaf(s4.z, w2.z, ac2.z); ac2.w = fmaf(s4.z, w2.w, ac2.w);
        ac2.x = fmaf(s4.w, w3.x, ac2.x); ac2.y = fmaf(s4.w, w3.y, ac2.y);
        ac2.z = fmaf(s4.w, w3.z, ac2.z); ac2.w = fmaf(s4.w, w3.w, ac2.w);
    }
    float4 hm;
    hm.x = fmaxf(ac2.x, 0.f); hm.y = fmaxf(ac2.y, 0.f);
    hm.z = fmaxf(ac2.z, 0.f); hm.w = fmaxf(ac2.w, 0.f);

    *(float4*)&sHS[sg][j0] = hst;
    *(float4*)&sHM[sg][j0] = hm;
    __syncwarp();

    // gate 2
    float4 ac3 = ldg4(bg2 + j0);
#pragma unroll 4
    for (int k = 0; k < 64; k++) {
        float vh = sHS[sg][k];
        float4 w = ldg4(Wg2 + k * 64 + j0);
        ac3.x = fmaf(vh, w.x, ac3.x); ac3.y = fmaf(vh, w.y, ac3.y);
        ac3.z = fmaf(vh, w.z, ac3.z); ac3.w = fmaf(vh, w.w, ac3.w);
    }
#pragma unroll 4
    for (int k = 0; k < 64; k++) {
        float vm = sHM[sg][k];
        float4 w = ldg4(Wg2 + (64 + k) * 64 + j0);
        ac3.x = fmaf(vm, w.x, ac3.x); ac3.y = fmaf(vm, w.y, ac3.y);
        ac3.z = fmaf(vm, w.z, ac3.z); ac3.w = fmaf(vm, w.w, ac3.w);
    }
    float4 g2;
    g2.x = 1.f / (1.f + expf(-ac3.x));
    g2.y = 1.f / (1.f + expf(-ac3.y));
    g2.z = 1.f / (1.f + expf(-ac3.z));
    g2.w = 1.f / (1.f + expf(-ac3.w));
    float4 h;
    h.x = g2.x * hst.x + (1.f - g2.x) * hm.x;
    h.y = g2.y * hst.y + (1.f - g2.y) * hm.y;
    h.z = g2.z * hst.z + (1.f - g2.z) * hm.z;
    h.w = g2.w * hst.w + (1.f - g2.w) * hm.w;

    // layernorm over 64 (16-lane shfl reduce)
    float s1 = (h.x + h.y) + (h.z + h.w);
    float s2 = (h.x * h.x + h.y * h.y) + (h.z * h.z + h.w * h.w);
#pragma unroll
    for (int m = 1; m < 16; m <<= 1) {
        s1 += __shfl_xor_sync(0xFFFFFFFFu, s1, m);
        s2 += __shfl_xor_sync(0xFFFFFFFFu, s2, m);
    }
    float mu  = s1 * (1.f / 64.f);
    float var = s2 * (1.f / 64.f) - mu * mu;
    float rstd = rsqrtf(var + 1e-5f);
    float4 lg = ldg4(ln_g + j0), lb = ldg4(ln_b + j0);
    float4 hn;
    hn.x = (h.x - mu) * rstd * lg.x + lb.x;
    hn.y = (h.y - mu) * rstd * lg.y + lb.y;
    hn.z = (h.z - mu) * rstd * lg.z + lb.z;
    hn.w = (h.w - mu) * rstd * lg.w + lb.w;

    // classifier (NCLS=2): Wc is [64,2]
    float4 wc0 = ldg4(Wc + j0 * 2);
    float4 wc1 = ldg4(Wc + j0 * 2 + 4);
    float o0 = hn.x * wc0.x + hn.y * wc0.z + hn.z * wc1.x + hn.w * wc1.z;
    float o1 = hn.x * wc0.y + hn.y * wc0.w + hn.z * wc1.y + hn.w * wc1.w;
#pragma unroll
    for (int m = 1; m < 16; m <<= 1) {
        o0 += __shfl_xor_sync(0xFFFFFFFFu, o0, m);
        o1 += __shfl_xor_sync(0xFFFFFFFFu, o1, m);
    }
    if (l == 0) {
        out[g * 2 + 0] = o0 + __ldg(bc + 0);
        out[g * 2 + 1] = o1 + __ldg(bc + 1);
    }
}

// ---------------- launch ----------------
extern "C" void kernel_launch(void* const* d_in, const int* in_sizes, int n_in,
                              void* d_out, int out_size) {
    const int*   ast_type  = (const int*)  d_in[0];
    const int*   ast_edge  = (const int*)  d_in[1];
    const int*   ast_batch = (const int*)  d_in[2];
    const int*   cfg_type  = (const int*)  d_in[3];
    const int*   cfg_edge  = (const int*)  d_in[4];
    const int*   cfg_batch = (const int*)  d_in[5];
    const float* sem       = (const float*)d_in[6];
    const float* ast_emb   = (const float*)d_in[7];
    const float* cfg_emb   = (const float*)d_in[8];
    const float* ast_W1    = (const float*)d_in[9];
    const float* ast_b1    = (const float*)d_in[10];
    const float* ast_W2    = (const float*)d_in[11];
    const float* ast_b2    = (const float*)d_in[12];
    const float* cfg_W1    = (const float*)d_in[13];
    const float* cfg_b1    = (const float*)d_in[14];
    const float* cfg_W2    = (const float*)d_in[15];
    const float* cfg_b2    = (const float*)d_in[16];
    const float* Wg1       = (const float*)d_in[17];
    const float* bg1       = (const float*)d_in[18];
    const float* Wsem      = (const float*)d_in[19];
    const float* bsem      = (const float*)d_in[20];
    const float* Wg2       = (const float*)d_in[21];
    const float* bg2       = (const float*)d_in[22];
    const float* ln_g      = (const float*)d_in[23];
    const float* ln_b      = (const float*)d_in[24];
    const float* Wc        = (const float*)d_in[25];
    const float* bc        = (const float*)d_in[26];
    float* out = (float*)d_out;

    k_init<<<ZBLK + 75, 256>>>(ast_emb, ast_W1, cfg_emb, cfg_W1);
    k_deg<<<(2 * (EMAX / 4) + 255) / 256, 256>>>(ast_edge, cfg_edge);
    k_scan1<<<2 * SCAN_NB, SCAN_B>>>();
    k_scan23<<<(2 * NMAX + 255) / 256, 256>>>(ast_type, cfg_type);
    k_fill<<<(2 * (EMAX / 4) + 255) / 256, 256>>>(ast_edge, cfg_edge);

    k_pull1<<<2 * NMAX / 32, 256>>>(ast_b1, cfg_b1);
    k_pull2<<<2 * NMAX / 32, 256>>>(ast_batch, cfg_batch);

    k_epilogue<<<NG / 8, 128>>>(sem, ast_batch, cfg_batch,
                                ast_W2, ast_b2, cfg_W2, cfg_b2,
                                Wg1, bg1, Wsem, bsem, Wg2, bg2,
                                ln_g, ln_b, Wc, bc, out);
}

// round 9
// speedup vs baseline: 2.0832x; 1.0001x over previous
#include <cuda_runtime.h>
#include <cuda_fp16.h>
#include <math.h>

#define NG 1024
#define SEM 768
#define NMAX 100000
#define EMAX 1250000
#define SCAN_B 512
#define SCAN_NB 196   // ceil(100000/512)
#define ZBLK 391      // ceil(NMAX/256)

// ---------------- device scratch (static, allocation-free) ----------------
__device__ int    g_deg   [2][NMAX];
__device__ int    g_rowptr[2][NMAX];
__device__ int    g_cursor[2][NMAX];
__device__ int    g_aggv  [2][SCAN_NB];
__device__ int    g_flag  [2][SCAN_NB];
__device__ int    g_csr   [2][EMAX];
__device__ int2   g_nd    [2][NMAX];      // {type, dinv bits}
__device__ uint4  g_x     [2][NMAX * 8];  // xd in fp16: 64 halves = 8 x uint4 /node
__device__ float4 g_pool  [2][NG * 16];
__device__ float  g_tab   [2][200 * 64];  // emb @ W1 lookup table

__device__ __forceinline__ void red_add_v4(float* addr, float4 v) {
    asm volatile("red.global.add.v4.f32 [%0], {%1, %2, %3, %4};"
                 :: "l"(addr), "f"(v.x), "f"(v.y), "f"(v.z), "f"(v.w)
                 : "memory");
}
__device__ __forceinline__ float4 ldg4(const float* p) {
    return __ldg((const float4*)p);
}

// ---------------- kernels ----------------

// init: blocks [0,ZBLK) zero deg/pool/scan-flags; blocks [ZBLK, ZBLK+75) build tab
__global__ void k_init(const float* __restrict__ embA, const float* __restrict__ W1A,
                       const float* __restrict__ embC, const float* __restrict__ W1C) {
    int b = blockIdx.x;
    if (b < ZBLK) {
        int i = b * 256 + threadIdx.x;
        if (i < NMAX) { g_deg[0][i] = 0; g_deg[1][i] = 0; }
        if (i < NG * 16) {
            g_pool[0][i] = make_float4(0.f, 0.f, 0.f, 0.f);
            g_pool[1][i] = make_float4(0.f, 0.f, 0.f, 0.f);
        }
        if (i < SCAN_NB) { g_flag[0][i] = 0; g_flag[1][i] = 0; }
    } else {
        __shared__ float sx[4][64];
        int sub = threadIdx.x >> 6, j = threadIdx.x & 63;
        int row = (b - ZBLK) * 4 + sub;   // 0..299 exactly
        const float* emb; const float* W; float* tab; int rr;
        if (row < 200) { emb = embA; W = W1A; tab = g_tab[0]; rr = row; }
        else           { emb = embC; W = W1C; tab = g_tab[1]; rr = row - 200; }
        sx[sub][j] = emb[rr * 64 + j];
        __syncthreads();
        float acc = 0.f;
#pragma unroll
        for (int k = 0; k < 64; k++) acc = fmaf(sx[sub][k], W[k * 64 + j], acc);
        tab[rr * 64 + j] = acc;
    }
}

// in-degree counts over dst, int4 = 4 edges per thread
__global__ void k_deg(const int* __restrict__ eA, const int* __restrict__ eC) {
    int t = blockIdx.x * blockDim.x + threadIdx.x;
    const int Q = EMAX / 4;            // 312500
    if (t >= 2 * Q) return;
    int s = t >= Q; int e = t - s * Q;
    const int4* dst4 = (const int4*)((s ? eC : eA) + EMAX);
    int4 q = __ldg(&dst4[e]);
    atomicAdd(&g_deg[s][q.x], 1);
    atomicAdd(&g_deg[s][q.y], 1);
    atomicAdd(&g_deg[s][q.z], 1);
    atomicAdd(&g_deg[s][q.w], 1);
}

// single-pass scan: block scan + publish aggregate + warp-parallel predecessor sum.
// Also finalizes rowptr/cursor and inits nd = {type, dinv}.
// 392 blocks x 512 thr: all co-resident (regs/smem small), so waiting on lower
// block indices cannot deadlock.
__global__ void __launch_bounds__(SCAN_B) k_scan(const int* __restrict__ tyA,
                                                 const int* __restrict__ tyC) {
    int s = blockIdx.x >= SCAN_NB;
    int blk = blockIdx.x - s * SCAN_NB;
    int i = blk * SCAN_B + threadIdx.x;
    int val = (i < NMAX) ? g_deg[s][i] : 0;
    __shared__ int sm[SCAN_B];
    __shared__ int s_prefix;
    sm[threadIdx.x] = val;
    __syncthreads();
#pragma unroll
    for (int off = 1; off < SCAN_B; off <<= 1) {
        int t = (threadIdx.x >= off) ? sm[threadIdx.x - off] : 0;
        __syncthreads();
        sm[threadIdx.x] += t;
        __syncthreads();
    }
    int incl = sm[threadIdx.x];

    if (threadIdx.x < 32) {
        int lane = threadIdx.x;
        if (lane == 0) {
            g_aggv[s][blk] = sm[SCAN_B - 1];
            __threadfence();
            atomicExch(&g_flag[s][blk], 1);
        }
        int run = 0;
        for (int wbase = blk - 1; wbase >= 0; wbase -= 32) {
            int p = wbase - lane;
            int c = 0;
            if (p >= 0) {
                while (atomicAdd(&g_flag[s][p], 0) == 0) { }
                c = atomicAdd(&g_aggv[s][p], 0);
            }
#pragma unroll
            for (int m = 16; m > 0; m >>= 1)
                c += __shfl_xor_sync(0xFFFFFFFFu, c, m);
            run += c;
        }
        if (lane == 0) s_prefix = run;
    }
    __syncthreads();

    if (i < NMAX) {
        int r = s_prefix + incl - val;
        g_rowptr[s][i] = r;
        g_cursor[s][i] = r;
        float dv = rsqrtf((float)val + 1.0f);
        int ty = __ldg((s ? tyC : tyA) + i);
        g_nd[s][i] = make_int2(ty, __float_as_int(dv));
    }
}

// CSR fill, int4 = 4 edges per thread
__global__ void k_fill(const int* __restrict__ eA, const int* __restrict__ eC) {
    int t = blockIdx.x * blockDim.x + threadIdx.x;
    const int Q = EMAX / 4;
    if (t >= 2 * Q) return;
    int s = t >= Q; int e = t - s * Q;
    const int* edge = s ? eC : eA;
    int4 us = __ldg((const int4*)edge + e);
    int4 vs = __ldg((const int4*)(edge + EMAX) + e);
    int* cur = g_cursor[s];
    int* csr = g_csr[s];
    csr[atomicAdd(&cur[vs.x], 1)] = us.x;
    csr[atomicAdd(&cur[vs.y], 1)] = us.y;
    csr[atomicAdd(&cur[vs.z], 1)] = us.z;
    csr[atomicAdd(&cur[vs.w], 1)] = us.w;
}

// pull layer 1, 8 lanes/node, 32 nodes/block (grid exact):
// xd_v = dinv_v * relu( dinv_v*(sum_u tab[ty_u]*dinv_u + tab[ty_v]*dinv_v) + b1 )
__global__ void __launch_bounds__(256) k_pull1(const float* __restrict__ b1A,
                                               const float* __restrict__ b1C) {
    int blk = blockIdx.x;              // 6250 blocks: 3125 per graph
    int s = blk >= 3125;
    int v = (blk - s * 3125) * 32 + (threadIdx.x >> 3);
    int l = threadIdx.x & 7;           // feature chunk: floats [8l, 8l+8)
    const float4* __restrict__ tab4 = (const float4*)g_tab[s];
    const int2* __restrict__ nd = g_nd[s];

    int2 ndv = __ldg(&nd[v]);
    float dv = __int_as_float(ndv.y);
    float a[8];
    {
        float4 t0 = tab4[ndv.x * 16 + l * 2];
        float4 t1 = tab4[ndv.x * 16 + l * 2 + 1];
        a[0] = t0.x * dv; a[1] = t0.y * dv; a[2] = t0.z * dv; a[3] = t0.w * dv;
        a[4] = t1.x * dv; a[5] = t1.y * dv; a[6] = t1.z * dv; a[7] = t1.w * dv;
    }

    int r = g_rowptr[s][v], d = g_deg[s][v];
    const int* __restrict__ cs = g_csr[s] + r;

#define NB1(u) do { \
        int2 n_ = __ldg(&nd[(u)]); \
        float du_ = __int_as_float(n_.y); \
        float4 p0_ = tab4[n_.x * 16 + l * 2]; \
        float4 p1_ = tab4[n_.x * 16 + l * 2 + 1]; \
        a[0] = fmaf(p0_.x, du_, a[0]); a[1] = fmaf(p0_.y, du_, a[1]); \
        a[2] = fmaf(p0_.z, du_, a[2]); a[3] = fmaf(p0_.w, du_, a[3]); \
        a[4] = fmaf(p1_.x, du_, a[4]); a[5] = fmaf(p1_.y, du_, a[5]); \
        a[6] = fmaf(p1_.z, du_, a[6]); a[7] = fmaf(p1_.w, du_, a[7]); \
    } while (0)

    int k = 0;
    int pe = (4 - (r & 3)) & 3; if (pe > d) pe = d;
    for (; k < pe; k++) NB1(__ldg(cs + k));
    for (; k + 4 <= d; k += 4) {
        int4 q = __ldg((const int4*)(cs + k));
        NB1(q.x); NB1(q.y); NB1(q.z); NB1(q.w);
    }
    for (; k < d; k++) NB1(__ldg(cs + k));
#undef NB1

    const float* b1 = s ? b1C : b1A;
    float4 b0 = ldg4(b1 + l * 8), b1v = ldg4(b1 + l * 8 + 4);
    float x0 = dv * fmaxf(fmaf(dv, a[0], b0.x), 0.f);
    float x1 = dv * fmaxf(fmaf(dv, a[1], b0.y), 0.f);
    float x2 = dv * fmaxf(fmaf(dv, a[2], b0.z), 0.f);
    float x3 = dv * fmaxf(fmaf(dv, a[3], b0.w), 0.f);
    float x4 = dv * fmaxf(fmaf(dv, a[4], b1v.x), 0.f);
    float x5 = dv * fmaxf(fmaf(dv, a[5], b1v.y), 0.f);
    float x6 = dv * fmaxf(fmaf(dv, a[6], b1v.z), 0.f);
    float x7 = dv * fmaxf(fmaf(dv, a[7], b1v.w), 0.f);
    __half2 h0 = __floats2half2_rn(x0, x1);
    __half2 h1 = __floats2half2_rn(x2, x3);
    __half2 h2 = __floats2half2_rn(x4, x5);
    __half2 h3 = __floats2half2_rn(x6, x7);
    uint4 u;
    u.x = *reinterpret_cast<unsigned int*>(&h0);
    u.y = *reinterpret_cast<unsigned int*>(&h1);
    u.z = *reinterpret_cast<unsigned int*>(&h2);
    u.w = *reinterpret_cast<unsigned int*>(&h3);
    g_x[s][v * 8 + l] = u;
}

// pull layer 2 + segmented pooling. 8 lanes/node, 32 nodes/block (grid exact).
// half2 accumulation (HADD2), dual accumulator sets to break the dep chain.
// val_v = dinv_v * (sum_u xd_u + xd_v); pool[batch_v] += val_v via smem segments.
__global__ void __launch_bounds__(256) k_pull2(const int* __restrict__ batchA,
                                               const int* __restrict__ batchC) {
    int blk = blockIdx.x;              // 6250 blocks: 3125 per graph
    int s = blk >= 3125;
    int v0 = (blk - s * 3125) * 32;
    int li = threadIdx.x >> 3;         // local node 0..31
    int l  = threadIdx.x & 7;          // feature chunk 0..7 (8 floats each)
    int v = v0 + li;

    const uint4* __restrict__ xd4 = (const uint4*)g_x[s];
    __half2 z = __float2half2_rn(0.f);
    __half2 ha0 = z, ha1 = z, ha2 = z, ha3 = z;
    __half2 hb0 = z, hb1 = z, hb2 = z, hb3 = z;

#define ACCA(q) do { __half2* h_ = reinterpret_cast<__half2*>(&(q)); \
        ha0 = __hadd2(ha0, h_[0]); ha1 = __hadd2(ha1, h_[1]); \
        ha2 = __hadd2(ha2, h_[2]); ha3 = __hadd2(ha3, h_[3]); } while (0)
#define ACCB(q) do { __half2* h_ = reinterpret_cast<__half2*>(&(q)); \
        hb0 = __hadd2(hb0, h_[0]); hb1 = __hadd2(hb1, h_[1]); \
        hb2 = __hadd2(hb2, h_[2]); hb3 = __hadd2(hb3, h_[3]); } while (0)

    uint4 qs = __ldg(&xd4[v * 8 + l]);   // self term
    ACCA(qs);
    int r = g_rowptr[s][v], d = g_deg[s][v];
    const int* __restrict__ cs = g_csr[s] + r;
    int k = 0;
    int pe = (4 - (r & 3)) & 3; if (pe > d) pe = d;
    for (; k < pe; k++) { uint4 q = __ldg(&xd4[__ldg(cs + k) * 8 + l]); ACCB(q); }
    for (; k + 4 <= d; k += 4) {
        int4 q = __ldg((const int4*)(cs + k));
        uint4 q0 = __ldg(&xd4[q.x * 8 + l]);
        uint4 q1 = __ldg(&xd4[q.y * 8 + l]);
        uint4 q2 = __ldg(&xd4[q.z * 8 + l]);
        uint4 q3 = __ldg(&xd4[q.w * 8 + l]);
        ACCA(q0); ACCB(q1); ACCA(q2); ACCB(q3);
    }
    for (; k < d; k++) { uint4 q = __ldg(&xd4[__ldg(cs + k) * 8 + l]); ACCA(q); }
#undef ACCA
#undef ACCB

    float2 p0 = __half22float2(__hadd2(ha0, hb0));
    float2 p1 = __half22float2(__hadd2(ha1, hb1));
    float2 p2 = __half22float2(__hadd2(ha2, hb2));
    float2 p3 = __half22float2(__hadd2(ha3, hb3));
    float dv = __int_as_float(__ldg(&g_nd[s][v]).y);

    __shared__ float sp[32][68];   // padded to break bank conflicts
    __shared__ int   sb[32];
    sp[li][l * 8 + 0] = p0.x * dv; sp[li][l * 8 + 1] = p0.y * dv;
    sp[li][l * 8 + 2] = p1.x * dv; sp[li][l * 8 + 3] = p1.y * dv;
    sp[li][l * 8 + 4] = p2.x * dv; sp[li][l * 8 + 5] = p2.y * dv;
    sp[li][l * 8 + 6] = p3.x * dv; sp[li][l * 8 + 7] = p3.y * dv;
    if (threadIdx.x < 32)
        sb[threadIdx.x] = __ldg((s ? batchC : batchA) + v0 + threadIdx.x);
    __syncthreads();

    int gId = sb[li];
    bool head = (li == 0) || (sb[li - 1] != gId);
    if (head) {
        int len = 1;
        while (li + len < 32 && sb[li + len] == gId) len++;
        float t0 = 0, t1 = 0, t2 = 0, t3 = 0, t4 = 0, t5 = 0, t6 = 0, t7 = 0;
        for (int j = li; j < li + len; j++) {
            t0 += sp[j][l * 8 + 0]; t1 += sp[j][l * 8 + 1];
            t2 += sp[j][l * 8 + 2]; t3 += sp[j][l * 8 + 3];
            t4 += sp[j][l * 8 + 4]; t5 += sp[j][l * 8 + 5];
            t6 += sp[j][l * 8 + 6]; t7 += sp[j][l * 8 + 7];
        }
        float* dst = (float*)&g_pool[s][gId * 16];
        red_add_v4(dst + l * 8,     make_float4(t0, t1, t2, t3));
        red_add_v4(dst + l * 8 + 4, make_float4(t4, t5, t6, t7));
    }
}

// count of nodes with batch==g in sorted array (two binary searches)
__device__ __forceinline__ int cnt_graph(const int* __restrict__ b, int g) {
    int lo = 0, hi = NMAX;
    while (lo < hi) { int m = (lo + hi) >> 1; if (__ldg(b + m) < g) lo = m + 1; else hi = m; }
    int lb = lo;
    lo = 0; hi = NMAX;
    while (lo < hi) { int m = (lo + hi) >> 1; if (__ldg(b + m) <= g) lo = m + 1; else hi = m; }
    return lo - lb;
}

// epilogue: 128 blocks x 128 thr; 8 graphs/block; 16 lanes x 4 cols per graph.
__global__ void __launch_bounds__(128) k_epilogue(
    const float* __restrict__ sem,
    const int* __restrict__ batchA, const int* __restrict__ batchC,
    const float* __restrict__ W2A, const float* __restrict__ b2A,
    const float* __restrict__ W2C, const float* __restrict__ b2C,
    const float* __restrict__ Wg1, const float* __restrict__ bg1,
    const float* __restrict__ Wsem, const float* __restrict__ bsem,
    const float* __restrict__ Wg2, const float* __restrict__ bg2,
    const float* __restrict__ ln_g, const float* __restrict__ ln_b,
    const float* __restrict__ Wc, const float* __restrict__ bc,
    float* __restrict__ out) {
    int sg = threadIdx.x >> 4;     // subgroup 0..7 (one graph each)
    int l  = threadIdx.x & 15;
    int g  = blockIdx.x * 8 + sg;
    int j0 = l * 4;

    __shared__ float sPA[8][64], sPC[8][64];
    __shared__ float sA [8][64], sB [8][64];
    __shared__ float sHS[8][64], sHM[8][64];

    float4 PA = g_pool[0][g * 16 + l];
    float4 PC = g_pool[1][g * 16 + l];
    *(float4*)&sPA[sg][j0] = PA;
    *(float4*)&sPC[sg][j0] = PC;
    float cntA = (float)cnt_graph(batchA, g);
    float cntC = (float)cnt_graph(batchC, g);
    __syncwarp();

    float4 a = make_float4(0.f, 0.f, 0.f, 0.f);
    float4 b = make_float4(0.f, 0.f, 0.f, 0.f);
#pragma unroll 4
    for (int k = 0; k < 64; k++) {
        float pa = sPA[sg][k], pc = sPC[sg][k];
        float4 wa = ldg4(W2A + k * 64 + j0);
        float4 wc = ldg4(W2C + k * 64 + j0);
        a.x = fmaf(pa, wa.x, a.x); a.y = fmaf(pa, wa.y, a.y);
        a.z = fmaf(pa, wa.z, a.z); a.w = fmaf(pa, wa.w, a.w);
        b.x = fmaf(pc, wc.x, b.x); b.y = fmaf(pc, wc.y, b.y);
        b.z = fmaf(pc, wc.z, b.z); b.w = fmaf(pc, wc.w, b.w);
    }
    {
        float4 ba = ldg4(b2A + j0), bb = ldg4(b2C + j0);
        a.x = fmaf(cntA, ba.x, a.x); a.y = fmaf(cntA, ba.y, a.y);
        a.z = fmaf(cntA, ba.z, a.z); a.w = fmaf(cntA, ba.w, a.w);
        b.x = fmaf(cntC, bb.x, b.x); b.y = fmaf(cntC, bb.y, b.y);
        b.z = fmaf(cntC, bb.z, b.z); b.w = fmaf(cntC, bb.w, b.w);
    }
    *(float4*)&sA[sg][j0] = a;
    *(float4*)&sB[sg][j0] = b;
    __syncwarp();

    // gate 1
    float4 acc = ldg4(bg1 + j0);
#pragma unroll 4
    for (int k = 0; k < 64; k++) {
        float va = sA[sg][k];
        float4 w = ldg4(Wg1 + k * 64 + j0);
        acc.x = fmaf(va, w.x, acc.x); acc.y = fmaf(va, w.y, acc.y);
        acc.z = fmaf(va, w.z, acc.z); acc.w = fmaf(va, w.w, acc.w);
    }
#pragma unroll 4
    for (int k = 0; k < 64; k++) {
        float vb = sB[sg][k];
        float4 w = ldg4(Wg1 + (64 + k) * 64 + j0);
        acc.x = fmaf(vb, w.x, acc.x); acc.y = fmaf(vb, w.y, acc.y);
        acc.z = fmaf(vb, w.z, acc.z); acc.w = fmaf(vb, w.w, acc.w);
    }
    float4 g1;
    g1.x = 1.f / (1.f + expf(-acc.x));
    g1.y = 1.f / (1.f + expf(-acc.y));
    g1.z = 1.f / (1.f + expf(-acc.z));
    g1.w = 1.f / (1.f + expf(-acc.w));
    float4 hst;
    hst.x = g1.x * a.x + (1.f - g1.x) * b.x;
    hst.y = g1.y * a.y + (1.f - g1.y) * b.y;
    hst.z = g1.z * a.z + (1.f - g1.z) * b.z;
    hst.w = g1.w * a.w + (1.f - g1.w) * b.w;

    // sem projection
    float4 ac2 = ldg4(bsem + j0);
    const float* semrow = sem + g * SEM;
#pragma unroll 4
    for (int k = 0; k < SEM; k += 4) {
        float4 s4 = ldg4(semrow + k);
        float4 w0 = ldg4(Wsem + (k + 0) * 64 + j0);
        float4 w1 = ldg4(Wsem + (k + 1) * 64 + j0);
        float4 w2 = ldg4(Wsem + (k + 2) * 64 + j0);
        float4 w3 = ldg4(Wsem + (k + 3) * 64 + j0);
        ac2.x = fmaf(s4.x, w0.x, ac2.x); ac2.y = fmaf(s4.x, w0.y, ac2.y);
        ac2.z = fmaf(s4.x, w0.z, ac2.z); ac2.w = fmaf(s4.x, w0.w, ac2.w);
        ac2.x = fmaf(s4.y, w1.x, ac2.x); ac2.y = fmaf(s4.y, w1.y, ac2.y);
        ac2.z = fmaf(s4.y, w1.z, ac2.z); ac2.w = fmaf(s4.y, w1.w, ac2.w);
        ac2.x = fmaf(s4.z, w2.x, ac2.x); ac2.y = fmaf(s4.z, w2.y, ac2.y);
        ac2.z = fmaf(s4.z, w2.z, ac2.z); ac2.w = fmaf(s4.z, w2.w, ac2.w);
        ac2.x = fmaf(s4.w, w3.x, ac2.x); ac2.y = fmaf(s4.w, w3.y, ac2.y);
        ac2.z = fmaf(s4.w, w3.z, ac2.z); ac2.w = fmaf(s4.w, w3.w, ac2.w);
    }
    float4 hm;
    hm.x = fmaxf(ac2.x, 0.f); hm.y = fmaxf(ac2.y, 0.f);
    hm.z = fmaxf(ac2.z, 0.f); hm.w = fmaxf(ac2.w, 0.f);

    *(float4*)&sHS[sg][j0] = hst;
    *(float4*)&sHM[sg][j0] = hm;
    __syncwarp();

    // gate 2
    float4 ac3 = ldg4(bg2 + j0);
#pragma unroll 4
    for (int k = 0; k < 64; k++) {
        float vh = sHS[sg][k];
        float4 w = ldg4(Wg2 + k * 64 + j0);
        ac3.x = fmaf(vh, w.x, ac3.x); ac3.y = fmaf(vh, w.y, ac3.y);
        ac3.z = fmaf(vh, w.z, ac3.z); ac3.w = fmaf(vh, w.w, ac3.w);
    }
#pragma unroll 4
    for (int k = 0; k < 64; k++) {
        float vm = sHM[sg][k];
        float4 w = ldg4(Wg2 + (64 + k) * 64 + j0);
        ac3.x = fmaf(vm, w.x, ac3.x); ac3.y = fmaf(vm, w.y, ac3.y);
        ac3.z = fmaf(vm, w.z, ac3.z); ac3.w = fmaf(vm, w.w, ac3.w);
    }
    float4 g2;
    g2.x = 1.f / (1.f + expf(-ac3.x));
    g2.y = 1.f / (1.f + expf(-ac3.y));
    g2.z = 1.f / (1.f + expf(-ac3.z));
    g2.w = 1.f / (1.f + expf(-ac3.w));
    float4 h;
    h.x = g2.x * hst.x + (1.f - g2.x) * hm.x;
    h.y = g2.y * hst.y + (1.f - g2.y) * hm.y;
    h.z = g2.z * hst.z + (1.f - g2.z) * hm.z;
    h.w = g2.w * hst.w + (1.f - g2.w) * hm.w;

    // layernorm over 64 (16-lane shfl reduce)
    float s1 = (h.x + h.y) + (h.z + h.w);
    float s2 = (h.x * h.x + h.y * h.y) + (h.z * h.z + h.w * h.w);
#pragma unroll
    for (int m = 1; m < 16; m <<= 1) {
        s1 += __shfl_xor_sync(0xFFFFFFFFu, s1, m);
        s2 += __shfl_xor_sync(0xFFFFFFFFu, s2, m);
    }
    float mu  = s1 * (1.f / 64.f);
    float var = s2 * (1.f / 64.f) - mu * mu;
    float rstd = rsqrtf(var + 1e-5f);
    float4 lg = ldg4(ln_g + j0), lb = ldg4(ln_b + j0);
    float4 hn;
    hn.x = (h.x - mu) * rstd * lg.x + lb.x;
    hn.y = (h.y - mu) * rstd * lg.y + lb.y;
    hn.z = (h.z - mu) * rstd * lg.z + lb.z;
    hn.w = (h.w - mu) * rstd * lg.w + lb.w;

    // classifier (NCLS=2): Wc is [64,2]
    float4 wc0 = ldg4(Wc + j0 * 2);
    float4 wc1 = ldg4(Wc + j0 * 2 + 4);
    float o0 = hn.x * wc0.x + hn.y * wc0.z + hn.z * wc1.x + hn.w * wc1.z;
    float o1 = hn.x * wc0.y + hn.y * wc0.w + hn.z * wc1.y + hn.w * wc1.w;
#pragma unroll
    for (int m = 1; m < 16; m <<= 1) {
        o0 += __shfl_xor_sync(0xFFFFFFFFu, o0, m);
        o1 += __shfl_xor_sync(0xFFFFFFFFu, o1, m);
    }
    if (l == 0) {
        out[g * 2 + 0] = o0 + __ldg(bc + 0);
        out[g * 2 + 1] = o1 + __ldg(bc + 1);
    }
}

// ---------------- launch ----------------
extern "C" void kernel_launch(void* const* d_in, const int* in_sizes, int n_in,
                              void* d_out, int out_size) {
    const int*   ast_type  = (const int*)  d_in[0];
    const int*   ast_edge  = (const int*)  d_in[1];
    const int*   ast_batch = (const int*)  d_in[2];
    const int*   cfg_type  = (const int*)  d_in[3];
    const int*   cfg_edge  = (const int*)  d_in[4];
    const int*   cfg_batch = (const int*)  d_in[5];
    const float* sem       = (const float*)d_in[6];
    const float* ast_emb   = (const float*)d_in[7];
    const float* cfg_emb   = (const float*)d_in[8];
    const float* ast_W1    = (const float*)d_in[9];
    const float* ast_b1    = (const float*)d_in[10];
    const float* ast_W2    = (const float*)d_in[11];
    const float* ast_b2    = (const float*)d_in[12];
    const float* cfg_W1    = (const float*)d_in[13];
    const float* cfg_b1    = (const float*)d_in[14];
    const float* cfg_W2    = (const float*)d_in[15];
    const float* cfg_b2    = (const float*)d_in[16];
    const float* Wg1       = (const float*)d_in[17];
    const float* bg1       = (const float*)d_in[18];
    const float* Wsem      = (const float*)d_in[19];
    const float* bsem      = (const float*)d_in[20];
    const float* Wg2       = (const float*)d_in[21];
    const float* bg2       = (const float*)d_in[22];
    const float* ln_g      = (const float*)d_in[23];
    const float* ln_b      = (const float*)d_in[24];
    const float* Wc        = (const float*)d_in[25];
    const float* bc        = (const float*)d_in[26];
    float* out = (float*)d_out;

    k_init<<<ZBLK + 75, 256>>>(ast_emb, ast_W1, cfg_emb, cfg_W1);
    k_deg<<<(2 * (EMAX / 4) + 255) / 256, 256>>>(ast_edge, cfg_edge);
    k_scan<<<2 * SCAN_NB, SCAN_B>>>(ast_type, cfg_type);
    k_fill<<<(2 * (EMAX / 4) + 255) / 256, 256>>>(ast_edge, cfg_edge);

    k_pull1<<<2 * NMAX / 32, 256>>>(ast_b1, cfg_b1);
    k_pull2<<<2 * NMAX / 32, 256>>>(ast_batch, cfg_batch);

    k_epilogue<<<NG / 8, 128>>>(sem, ast_batch, cfg_batch,
                                ast_W2, ast_b2, cfg_W2, cfg_b2,
                                Wg1, bg1, Wsem, bsem, Wg2, bg2,
                                ln_g, ln_b, Wc, bc, out);
}